// round 6
// baseline (speedup 1.0000x reference)
#include <cuda_runtime.h>
#include <cuda_bf16.h>
#include <cstdint>

// Problem constants (fixed by the dataset)
#define F_IN   512
#define F_OUT  128
#define MAX_N  50048
#define MAX_E  1700000

// Scratch for x = (features * drop_mask) @ W   [N, F_OUT]
__device__ float g_x[(size_t)MAX_N * F_OUT];

// Pre-split W (bf16 hi/lo), computed once per launch
__device__ __nv_bfloat16 g_Wh[F_IN * F_OUT];
__device__ __nv_bfloat16 g_Wl[F_IN * F_OUT];

// CSR scratch
__device__ int   g_deg[MAX_N];
__device__ int   g_row_start[MAX_N + 1];
__device__ int   g_cursor[MAX_N];
__device__ int   g_blk_sum[512];
__device__ uint2 g_edges[MAX_E];   // .x = col, .y = bits(val)

// ---------------------------------------------------------------------------
// MMA helpers
// ---------------------------------------------------------------------------
#define BM 128
#define BK 32
#define LDA 40    // As row length (bf16) with +8 pad: conflict-free ldmatrix
#define LDB 136   // Ws row length (bf16) with +8 pad

__device__ __forceinline__ void ldm_x4(uint32_t* f, uint32_t addr)
{
    asm volatile("ldmatrix.sync.aligned.m8n8.x4.shared.b16 {%0,%1,%2,%3}, [%4];"
                 : "=r"(f[0]), "=r"(f[1]), "=r"(f[2]), "=r"(f[3]) : "r"(addr));
}

__device__ __forceinline__ void ldm_x4_trans(uint32_t* f, uint32_t addr)
{
    asm volatile("ldmatrix.sync.aligned.m8n8.x4.trans.shared.b16 {%0,%1,%2,%3}, [%4];"
                 : "=r"(f[0]), "=r"(f[1]), "=r"(f[2]), "=r"(f[3]) : "r"(addr));
}

__device__ __forceinline__ void mma_bf16(float* c, const uint32_t* a,
                                         uint32_t b0, uint32_t b1)
{
    asm volatile(
        "mma.sync.aligned.m16n8k16.row.col.f32.bf16.bf16.f32 "
        "{%0,%1,%2,%3}, {%4,%5,%6,%7}, {%8,%9}, {%0,%1,%2,%3};"
        : "+f"(c[0]), "+f"(c[1]), "+f"(c[2]), "+f"(c[3])
        : "r"(a[0]), "r"(a[1]), "r"(a[2]), "r"(a[3]), "r"(b0), "r"(b1));
}

__device__ __forceinline__ uint32_t smem_u32(const void* p)
{
    uint32_t r;
    asm("{.reg .u64 t; cvta.to.shared.u64 t, %1; cvt.u32.u64 %0, t;}"
        : "=r"(r) : "l"(p));
    return r;
}

// pack high 16 bits of two fp32 values -> bf16x2 (RZ truncation; 1 PRMT)
__device__ __forceinline__ uint32_t prmt_hi(uint32_t a, uint32_t b)
{
    uint32_t r;
    asm("prmt.b32 %0, %1, %2, 0x7632;" : "=r"(r) : "r"(a), "r"(b));
    return r;
}

// pack two fp32 -> bf16x2 (RN), e0 in low half
__device__ __forceinline__ uint32_t cvt_bf16x2(float e0, float e1)
{
    uint32_t r;
    asm("cvt.rn.bf16x2.f32 %0, %1, %2;" : "=r"(r) : "f"(e1), "f"(e0));
    return r;
}

// ---------------------------------------------------------------------------
// Kernel 0: split W into hi (bf16 RZ-truncation) and lo (bf16 RN of residual)
// ---------------------------------------------------------------------------
__global__ void w_split_kernel(const float* __restrict__ W)
{
    int i = blockIdx.x * blockDim.x + threadIdx.x;
    if (i < F_IN * F_OUT) {
        float w = W[i];
        uint32_t wb = __float_as_uint(w);
        float hi = __uint_as_float(wb & 0xffff0000u);
        float lo = w - hi;
        g_Wh[i] = __ushort_as_bfloat16((unsigned short)(wb >> 16));
        g_Wl[i] = __float2bfloat16(lo);
    }
}

// ---------------------------------------------------------------------------
// Kernel 1: fused dropout + split-bf16 tensor-core GEMM
// x ~= Ah*Wh + Ah*Wl + Al*Wh  (fp32 accum; err ~1e-5)
// Tiles: BM=128, BN=128, BK=32; 256 threads = 8 warps (4 M x 2 N),
// each warp computes 32x64 via m16n8k16 mma.sync.
// ---------------------------------------------------------------------------
__global__ __launch_bounds__(256)
void gemm_dropout_mma_kernel(const float* __restrict__ A,
                             const float* __restrict__ Mk,
                             int M)
{
    __shared__ __nv_bfloat16 As_hi[BM][LDA];
    __shared__ __nv_bfloat16 As_lo[BM][LDA];
    __shared__ __nv_bfloat16 Ws_hi[BK][LDB];
    __shared__ __nv_bfloat16 Ws_lo[BK][LDB];

    const int tid  = threadIdx.x;
    const int warp = tid >> 5;
    const int lane = tid & 31;
    const int block_m = blockIdx.x * BM;

    const int wm = (warp & 3) * 32;   // warp m-offset (0,32,64,96)
    const int wn = (warp >> 2) * 64;  // warp n-offset (0,64)

    const int aRow = lane & 15;
    const int aOff = (lane >> 4) * 8;

    float acc[2][8][4];
#pragma unroll
    for (int mt = 0; mt < 2; mt++)
#pragma unroll
        for (int nt = 0; nt < 8; nt++)
#pragma unroll
            for (int q = 0; q < 4; q++) acc[mt][nt][q] = 0.f;

    const uint32_t as_hi_b = smem_u32(&As_hi[0][0]);
    const uint32_t as_lo_b = smem_u32(&As_lo[0][0]);
    const uint32_t ws_hi_b = smem_u32(&Ws_hi[0][0]);
    const uint32_t ws_lo_b = smem_u32(&Ws_lo[0][0]);

    for (int k0 = 0; k0 < F_IN; k0 += BK) {
        // ---- fill A tiles: 128x32 fp32, fused dropout, cheap hi/lo split ----
#pragma unroll
        for (int p = 0; p < 4; p++) {
            int idx = p * 256 + tid;
            int row = idx >> 3;            // 0..127
            int col = (idx & 7) * 4;       // 0..28
            int gm  = block_m + row;
            float4 e = make_float4(0.f, 0.f, 0.f, 0.f);
            if (gm < M) {
                const float4 a = *(const float4*)(A  + (size_t)gm * F_IN + k0 + col);
                const float4 m = *(const float4*)(Mk + (size_t)gm * F_IN + k0 + col);
                e = make_float4(a.x * m.x, a.y * m.y, a.z * m.z, a.w * m.w);
            }
            const uint32_t b0 = __float_as_uint(e.x);
            const uint32_t b1 = __float_as_uint(e.y);
            const uint32_t b2 = __float_as_uint(e.z);
            const uint32_t b3 = __float_as_uint(e.w);
            const float lo0 = e.x - __uint_as_float(b0 & 0xffff0000u);
            const float lo1 = e.y - __uint_as_float(b1 & 0xffff0000u);
            const float lo2 = e.z - __uint_as_float(b2 & 0xffff0000u);
            const float lo3 = e.w - __uint_as_float(b3 & 0xffff0000u);
            uint2 hw, lw;
            hw.x = prmt_hi(b0, b1);     hw.y = prmt_hi(b2, b3);
            lw.x = cvt_bf16x2(lo0, lo1); lw.y = cvt_bf16x2(lo2, lo3);
            *(uint2*)&As_hi[row][col] = hw;
            *(uint2*)&As_lo[row][col] = lw;
        }
        // ---- fill W tiles: plain bf16 copies of precomputed split ----
#pragma unroll
        for (int p = 0; p < 2; p++) {
            int idx = p * 256 + tid;       // 0..511
            int row = idx >> 4;            // 0..31
            int q   = (idx & 15) * 8;      // bf16 index in row
            const size_t go = (size_t)(k0 + row) * F_OUT + q;
            *(uint4*)&Ws_hi[row][q] = *(const uint4*)(g_Wh + go);
            *(uint4*)&Ws_lo[row][q] = *(const uint4*)(g_Wl + go);
        }
        __syncthreads();

        // ---- compute: two k16 steps per chunk ----
#pragma unroll
        for (int k16 = 0; k16 < BK; k16 += 16) {
            uint32_t ah[2][4], al[2][4];
#pragma unroll
            for (int mt = 0; mt < 2; mt++) {
                int r = wm + mt * 16 + aRow;
                int c = k16 + aOff;
                ldm_x4(ah[mt], as_hi_b + (uint32_t)(r * LDA + c) * 2);
                ldm_x4(al[mt], as_lo_b + (uint32_t)(r * LDA + c) * 2);
            }
            uint32_t bh[4][4], bl[4][4];
#pragma unroll
            for (int nq = 0; nq < 4; nq++) {
                int kr = k16 + (lane & 15);
                int c  = wn + nq * 16 + aOff;
                ldm_x4_trans(bh[nq], ws_hi_b + (uint32_t)(kr * LDB + c) * 2);
                ldm_x4_trans(bl[nq], ws_lo_b + (uint32_t)(kr * LDB + c) * 2);
            }
#pragma unroll
            for (int mt = 0; mt < 2; mt++) {
#pragma unroll
                for (int nt = 0; nt < 8; nt++) {
                    const int nq = nt >> 1, pr = (nt & 1) * 2;
                    mma_bf16(acc[mt][nt], ah[mt], bh[nq][pr], bh[nq][pr + 1]);
                    mma_bf16(acc[mt][nt], ah[mt], bl[nq][pr], bl[nq][pr + 1]);
                    mma_bf16(acc[mt][nt], al[mt], bh[nq][pr], bh[nq][pr + 1]);
                }
            }
        }
        __syncthreads();
    }

    // ---- store x tile ----
    const int gid = lane >> 2;
    const int tq  = lane & 3;
#pragma unroll
    for (int mt = 0; mt < 2; mt++) {
        int gm0 = block_m + wm + mt * 16 + gid;
        int gm1 = gm0 + 8;
#pragma unroll
        for (int nt = 0; nt < 8; nt++) {
            int col = wn + nt * 8 + tq * 2;
            if (gm0 < M)
                *(float2*)(g_x + (size_t)gm0 * F_OUT + col) =
                    make_float2(acc[mt][nt][0], acc[mt][nt][1]);
            if (gm1 < M)
                *(float2*)(g_x + (size_t)gm1 * F_OUT + col) =
                    make_float2(acc[mt][nt][2], acc[mt][nt][3]);
        }
    }
}

// ---------------------------------------------------------------------------
// CSR build
// ---------------------------------------------------------------------------
__global__ void zero_deg_kernel(int N)
{
    int i = blockIdx.x * blockDim.x + threadIdx.x;
    if (i < N) g_deg[i] = 0;
}

__global__ void hist_kernel(const int* __restrict__ rows, int E)
{
    int i = blockIdx.x * blockDim.x + threadIdx.x;
    if (i < E) atomicAdd(&g_deg[rows[i]], 1);
}

__global__ __launch_bounds__(256)
void scan_blocks_kernel(int N)
{
    __shared__ int sh[256];
    const int tid = threadIdx.x;
    const int i = blockIdx.x * 256 + tid;

    int v = (i < N) ? g_deg[i] : 0;
    int incl = v;
    sh[tid] = incl;
    __syncthreads();
#pragma unroll
    for (int off = 1; off < 256; off <<= 1) {
        int t = (tid >= off) ? sh[tid - off] : 0;
        __syncthreads();
        incl += t;
        sh[tid] = incl;
        __syncthreads();
    }
    if (i < N) g_row_start[i] = incl - v;
    if (tid == 255) g_blk_sum[blockIdx.x] = incl;
}

__global__ __launch_bounds__(512)
void scan_top_kernel(int nblocks)
{
    __shared__ int sh[512];
    const int tid = threadIdx.x;
    int v = (tid < nblocks) ? g_blk_sum[tid] : 0;
    int incl = v;
    sh[tid] = incl;
    __syncthreads();
#pragma unroll
    for (int off = 1; off < 512; off <<= 1) {
        int t = (tid >= off) ? sh[tid - off] : 0;
        __syncthreads();
        incl += t;
        sh[tid] = incl;
        __syncthreads();
    }
    if (tid < nblocks) g_blk_sum[tid] = incl - v;
}

__global__ __launch_bounds__(256)
void scan_add_kernel(int N, int E)
{
    const int i = blockIdx.x * 256 + threadIdx.x;
    if (i < N) {
        int rs = g_row_start[i] + g_blk_sum[blockIdx.x];
        g_row_start[i] = rs;
        g_cursor[i]    = rs;
    }
    if (i == 0) g_row_start[N] = E;
}

__global__ void fill_kernel(const int*   __restrict__ rows,
                            const int*   __restrict__ cols,
                            const float* __restrict__ vals,
                            int E)
{
    int i = blockIdx.x * blockDim.x + threadIdx.x;
    if (i < E) {
        int pos = atomicAdd(&g_cursor[rows[i]], 1);
        g_edges[pos] = make_uint2((unsigned)cols[i], __float_as_uint(vals[i]));
    }
}

// ---------------------------------------------------------------------------
// Kernel 5: row-parallel SpMM + bias + ReLU (one warp per output row)
// ---------------------------------------------------------------------------
__global__ __launch_bounds__(256)
void spmm_csr_kernel(const float* __restrict__ b,
                     float*       __restrict__ out,
                     int N)
{
    const int warp_in_blk = threadIdx.x >> 5;
    const int lane = threadIdx.x & 31;
    const int row  = blockIdx.x * 8 + warp_in_blk;
    if (row >= N) return;

    const int s = g_row_start[row];
    const int e = g_row_start[row + 1];

    float4 acc = make_float4(0.f, 0.f, 0.f, 0.f);

    int j = s;
    for (; j + 4 <= e; j += 4) {
        const uint2 e0 = g_edges[j];
        const uint2 e1 = g_edges[j + 1];
        const uint2 e2 = g_edges[j + 2];
        const uint2 e3 = g_edges[j + 3];
        const float4 a0 = __ldg((const float4*)(g_x + (size_t)e0.x * F_OUT) + lane);
        const float4 a1 = __ldg((const float4*)(g_x + (size_t)e1.x * F_OUT) + lane);
        const float4 a2 = __ldg((const float4*)(g_x + (size_t)e2.x * F_OUT) + lane);
        const float4 a3 = __ldg((const float4*)(g_x + (size_t)e3.x * F_OUT) + lane);
        const float v0 = __uint_as_float(e0.y);
        const float v1 = __uint_as_float(e1.y);
        const float v2 = __uint_as_float(e2.y);
        const float v3 = __uint_as_float(e3.y);
        acc.x = fmaf(v0, a0.x, acc.x); acc.y = fmaf(v0, a0.y, acc.y);
        acc.z = fmaf(v0, a0.z, acc.z); acc.w = fmaf(v0, a0.w, acc.w);
        acc.x = fmaf(v1, a1.x, acc.x); acc.y = fmaf(v1, a1.y, acc.y);
        acc.z = fmaf(v1, a1.z, acc.z); acc.w = fmaf(v1, a1.w, acc.w);
        acc.x = fmaf(v2, a2.x, acc.x); acc.y = fmaf(v2, a2.y, acc.y);
        acc.z = fmaf(v2, a2.z, acc.z); acc.w = fmaf(v2, a2.w, acc.w);
        acc.x = fmaf(v3, a3.x, acc.x); acc.y = fmaf(v3, a3.y, acc.y);
        acc.z = fmaf(v3, a3.z, acc.z); acc.w = fmaf(v3, a3.w, acc.w);
    }
    for (; j < e; j++) {
        const uint2 e0 = g_edges[j];
        const float4 a0 = __ldg((const float4*)(g_x + (size_t)e0.x * F_OUT) + lane);
        const float v0 = __uint_as_float(e0.y);
        acc.x = fmaf(v0, a0.x, acc.x); acc.y = fmaf(v0, a0.y, acc.y);
        acc.z = fmaf(v0, a0.z, acc.z); acc.w = fmaf(v0, a0.w, acc.w);
    }

    const float4 bb = ((const float4*)b)[lane];
    float4 r;
    r.x = fmaxf(acc.x + bb.x, 0.f);
    r.y = fmaxf(acc.y + bb.y, 0.f);
    r.z = fmaxf(acc.z + bb.z, 0.f);
    r.w = fmaxf(acc.w + bb.w, 0.f);
    ((float4*)(out + (size_t)row * F_OUT))[lane] = r;
}

// ---------------------------------------------------------------------------
extern "C" void kernel_launch(void* const* d_in, const int* in_sizes, int n_in,
                              void* d_out, int out_size)
{
    const float* features  = (const float*)d_in[0];  // [N, 512]
    const float* drop_mask = (const float*)d_in[1];  // [N, 512]
    const float* W         = (const float*)d_in[2];  // [512, 128]
    const float* b         = (const float*)d_in[3];  // [128]
    const int*   adj_rows  = (const int*)d_in[4];    // [E]
    const int*   adj_cols  = (const int*)d_in[5];    // [E]
    const float* adj_vals  = (const float*)d_in[6];  // [E]
    float* out = (float*)d_out;                      // [N, 128]

    const int M = in_sizes[0] / F_IN;
    const int E = in_sizes[4];
    const int nscan = (M + 255) / 256;

    // 0) split W once
    w_split_kernel<<<(F_IN * F_OUT + 255) / 256, 256>>>(W);

    // 1) x = (features * drop_mask) @ W   (split-bf16 tensor cores)
    gemm_dropout_mma_kernel<<<(M + BM - 1) / BM, 256>>>(features, drop_mask, M);

    // 2) CSR build (parallel 3-phase scan)
    zero_deg_kernel<<<(M + 255) / 256, 256>>>(M);
    hist_kernel<<<(E + 255) / 256, 256>>>(adj_rows, E);
    scan_blocks_kernel<<<nscan, 256>>>(M);
    scan_top_kernel<<<1, 512>>>(nscan);
    scan_add_kernel<<<nscan, 256>>>(M, E);
    fill_kernel<<<(E + 255) / 256, 256>>>(adj_rows, adj_cols, adj_vals, E);

    // 3) row-parallel SpMM + bias + ReLU
    spmm_csr_kernel<<<(M + 7) / 8, 256>>>(b, out, M);
}

// round 7
// speedup vs baseline: 1.2847x; 1.2847x over previous
#include <cuda_runtime.h>
#include <cuda_bf16.h>
#include <cstdint>

// Problem constants (fixed by the dataset)
#define F_IN   512
#define F_OUT  128
#define MAX_N  50048
#define MAX_E  1700000

// Scratch for x = (features * drop_mask) @ W   [N, F_OUT]
__device__ float g_x[(size_t)MAX_N * F_OUT];

// Pre-split W (bf16 hi/lo), computed once per launch
__device__ __nv_bfloat16 g_Wh[F_IN * F_OUT];
__device__ __nv_bfloat16 g_Wl[F_IN * F_OUT];

// CSR scratch
__device__ int   g_deg[MAX_N];
__device__ int   g_row_start[MAX_N + 1];
__device__ int   g_cursor[MAX_N];
__device__ int   g_blk_sum[512];
__device__ uint2 g_edges[MAX_E];   // .x = col, .y = bits(val)

// ---------------------------------------------------------------------------
// MMA helpers
// ---------------------------------------------------------------------------
#define BM 128
#define BK 32
#define LDA 40    // As row length (bf16) with +8 pad: conflict-free ldmatrix
#define LDB 136   // Ws row length (bf16) with +8 pad

__device__ __forceinline__ void ldm_x4(uint32_t* f, uint32_t addr)
{
    asm volatile("ldmatrix.sync.aligned.m8n8.x4.shared.b16 {%0,%1,%2,%3}, [%4];"
                 : "=r"(f[0]), "=r"(f[1]), "=r"(f[2]), "=r"(f[3]) : "r"(addr));
}

__device__ __forceinline__ void ldm_x4_trans(uint32_t* f, uint32_t addr)
{
    asm volatile("ldmatrix.sync.aligned.m8n8.x4.trans.shared.b16 {%0,%1,%2,%3}, [%4];"
                 : "=r"(f[0]), "=r"(f[1]), "=r"(f[2]), "=r"(f[3]) : "r"(addr));
}

__device__ __forceinline__ void mma_bf16(float* c, const uint32_t* a,
                                         uint32_t b0, uint32_t b1)
{
    asm volatile(
        "mma.sync.aligned.m16n8k16.row.col.f32.bf16.bf16.f32 "
        "{%0,%1,%2,%3}, {%4,%5,%6,%7}, {%8,%9}, {%0,%1,%2,%3};"
        : "+f"(c[0]), "+f"(c[1]), "+f"(c[2]), "+f"(c[3])
        : "r"(a[0]), "r"(a[1]), "r"(a[2]), "r"(a[3]), "r"(b0), "r"(b1));
}

__device__ __forceinline__ uint32_t smem_u32(const void* p)
{
    uint32_t r;
    asm("{.reg .u64 t; cvta.to.shared.u64 t, %1; cvt.u32.u64 %0, t;}"
        : "=r"(r) : "l"(p));
    return r;
}

__device__ __forceinline__ uint32_t pack_bf16x2(float lo_val, float hi_val)
{
    __nv_bfloat162 h = __floats2bfloat162_rn(lo_val, hi_val);
    return *(uint32_t*)&h;
}

// ---------------------------------------------------------------------------
// Kernel 0: split W into hi (bf16 RN) and lo (bf16 RN of residual)
// ---------------------------------------------------------------------------
__global__ void w_split_kernel(const float* __restrict__ W)
{
    int i = blockIdx.x * blockDim.x + threadIdx.x;
    if (i < F_IN * F_OUT) {
        float w = W[i];
        __nv_bfloat16 h = __float2bfloat16(w);
        float lo = w - __bfloat162float(h);
        g_Wh[i] = h;
        g_Wl[i] = __float2bfloat16(lo);
    }
}

// ---------------------------------------------------------------------------
// Kernel 1: fused dropout + split-bf16 tensor-core GEMM  (A path = R5 exact)
// x ~= Ah*Wh + Ah*Wl + Al*Wh  (fp32 accum; err ~1e-5)
// Tiles: BM=128, BN=128, BK=32; 256 threads = 8 warps (4 M x 2 N),
// each warp computes 32x64 via m16n8k16 mma.sync.
// ---------------------------------------------------------------------------
__global__ __launch_bounds__(256)
void gemm_dropout_mma_kernel(const float* __restrict__ A,
                             const float* __restrict__ Mk,
                             int M)
{
    __shared__ __nv_bfloat16 As_hi[BM][LDA];
    __shared__ __nv_bfloat16 As_lo[BM][LDA];
    __shared__ __nv_bfloat16 Ws_hi[BK][LDB];
    __shared__ __nv_bfloat16 Ws_lo[BK][LDB];

    const int tid  = threadIdx.x;
    const int warp = tid >> 5;
    const int lane = tid & 31;
    const int block_m = blockIdx.x * BM;

    const int wm = (warp & 3) * 32;   // warp m-offset (0,32,64,96)
    const int wn = (warp >> 2) * 64;  // warp n-offset (0,64)

    const int aRow = lane & 15;
    const int aOff = (lane >> 4) * 8;

    float acc[2][8][4];
#pragma unroll
    for (int mt = 0; mt < 2; mt++)
#pragma unroll
        for (int nt = 0; nt < 8; nt++)
#pragma unroll
            for (int q = 0; q < 4; q++) acc[mt][nt][q] = 0.f;

    const uint32_t as_hi_b = smem_u32(&As_hi[0][0]);
    const uint32_t as_lo_b = smem_u32(&As_lo[0][0]);
    const uint32_t ws_hi_b = smem_u32(&Ws_hi[0][0]);
    const uint32_t ws_lo_b = smem_u32(&Ws_lo[0][0]);

    for (int k0 = 0; k0 < F_IN; k0 += BK) {
        // ---- fill A tiles: 128x32 fp32, fused dropout, split to hi/lo ----
        // (exactly the R5 path)
#pragma unroll
        for (int p = 0; p < 4; p++) {
            int idx = p * 256 + tid;
            int row = idx >> 3;            // 0..127
            int col = (idx & 7) * 4;       // 0..28
            int gm  = block_m + row;
            float4 e = make_float4(0.f, 0.f, 0.f, 0.f);
            if (gm < M) {
                const float4 a = *(const float4*)(A  + (size_t)gm * F_IN + k0 + col);
                const float4 m = *(const float4*)(Mk + (size_t)gm * F_IN + k0 + col);
                e = make_float4(a.x * m.x, a.y * m.y, a.z * m.z, a.w * m.w);
            }
            float eh[4], el[4];
            const float ev[4] = {e.x, e.y, e.z, e.w};
#pragma unroll
            for (int q = 0; q < 4; q++) {
                __nv_bfloat16 h = __float2bfloat16(ev[q]);
                eh[q] = __bfloat162float(h);
                el[q] = ev[q] - eh[q];
            }
            uint2 hw, lw;
            hw.x = pack_bf16x2(eh[0], eh[1]); hw.y = pack_bf16x2(eh[2], eh[3]);
            lw.x = pack_bf16x2(el[0], el[1]); lw.y = pack_bf16x2(el[2], el[3]);
            *(uint2*)&As_hi[row][col] = hw;
            *(uint2*)&As_lo[row][col] = lw;
        }
        // ---- fill W tiles: plain bf16 copies of precomputed split ----
#pragma unroll
        for (int p = 0; p < 2; p++) {
            int idx = p * 256 + tid;       // 0..511
            int row = idx >> 4;            // 0..31
            int q   = (idx & 15) * 8;      // bf16 index in row
            const size_t go = (size_t)(k0 + row) * F_OUT + q;
            *(uint4*)&Ws_hi[row][q] = *(const uint4*)(g_Wh + go);
            *(uint4*)&Ws_lo[row][q] = *(const uint4*)(g_Wl + go);
        }
        __syncthreads();

        // ---- compute: two k16 steps per chunk ----
#pragma unroll
        for (int k16 = 0; k16 < BK; k16 += 16) {
            uint32_t ah[2][4], al[2][4];
#pragma unroll
            for (int mt = 0; mt < 2; mt++) {
                int r = wm + mt * 16 + aRow;
                int c = k16 + aOff;
                ldm_x4(ah[mt], as_hi_b + (uint32_t)(r * LDA + c) * 2);
                ldm_x4(al[mt], as_lo_b + (uint32_t)(r * LDA + c) * 2);
            }
            uint32_t bh[4][4], bl[4][4];
#pragma unroll
            for (int nq = 0; nq < 4; nq++) {
                int kr = k16 + (lane & 15);
                int c  = wn + nq * 16 + aOff;
                ldm_x4_trans(bh[nq], ws_hi_b + (uint32_t)(kr * LDB + c) * 2);
                ldm_x4_trans(bl[nq], ws_lo_b + (uint32_t)(kr * LDB + c) * 2);
            }
#pragma unroll
            for (int mt = 0; mt < 2; mt++) {
#pragma unroll
                for (int nt = 0; nt < 8; nt++) {
                    const int nq = nt >> 1, pr = (nt & 1) * 2;
                    mma_bf16(acc[mt][nt], ah[mt], bh[nq][pr], bh[nq][pr + 1]);
                    mma_bf16(acc[mt][nt], ah[mt], bl[nq][pr], bl[nq][pr + 1]);
                    mma_bf16(acc[mt][nt], al[mt], bh[nq][pr], bh[nq][pr + 1]);
                }
            }
        }
        __syncthreads();
    }

    // ---- store x tile ----
    const int gid = lane >> 2;
    const int tq  = lane & 3;
#pragma unroll
    for (int mt = 0; mt < 2; mt++) {
        int gm0 = block_m + wm + mt * 16 + gid;
        int gm1 = gm0 + 8;
#pragma unroll
        for (int nt = 0; nt < 8; nt++) {
            int col = wn + nt * 8 + tq * 2;
            if (gm0 < M)
                *(float2*)(g_x + (size_t)gm0 * F_OUT + col) =
                    make_float2(acc[mt][nt][0], acc[mt][nt][1]);
            if (gm1 < M)
                *(float2*)(g_x + (size_t)gm1 * F_OUT + col) =
                    make_float2(acc[mt][nt][2], acc[mt][nt][3]);
        }
    }
}

// ---------------------------------------------------------------------------
// CSR build
// ---------------------------------------------------------------------------
__global__ void zero_deg_kernel(int N)
{
    int i = blockIdx.x * blockDim.x + threadIdx.x;
    if (i < N) g_deg[i] = 0;
}

// hist: 4 edges per thread (int4) for MLP
__global__ void hist_kernel(const int* __restrict__ rows, int E)
{
    int i4 = (blockIdx.x * blockDim.x + threadIdx.x) * 4;
    if (i4 + 3 < E) {
        const int4 r = *(const int4*)(rows + i4);
        atomicAdd(&g_deg[r.x], 1);
        atomicAdd(&g_deg[r.y], 1);
        atomicAdd(&g_deg[r.z], 1);
        atomicAdd(&g_deg[r.w], 1);
    } else {
        for (int i = i4; i < E; i++) atomicAdd(&g_deg[rows[i]], 1);
    }
}

__global__ __launch_bounds__(256)
void scan_blocks_kernel(int N)
{
    __shared__ int sh[256];
    const int tid = threadIdx.x;
    const int i = blockIdx.x * 256 + tid;

    int v = (i < N) ? g_deg[i] : 0;
    int incl = v;
    sh[tid] = incl;
    __syncthreads();
#pragma unroll
    for (int off = 1; off < 256; off <<= 1) {
        int t = (tid >= off) ? sh[tid - off] : 0;
        __syncthreads();
        incl += t;
        sh[tid] = incl;
        __syncthreads();
    }
    if (i < N) g_row_start[i] = incl - v;
    if (tid == 255) g_blk_sum[blockIdx.x] = incl;
}

__global__ __launch_bounds__(512)
void scan_top_kernel(int nblocks)
{
    __shared__ int sh[512];
    const int tid = threadIdx.x;
    int v = (tid < nblocks) ? g_blk_sum[tid] : 0;
    int incl = v;
    sh[tid] = incl;
    __syncthreads();
#pragma unroll
    for (int off = 1; off < 512; off <<= 1) {
        int t = (tid >= off) ? sh[tid - off] : 0;
        __syncthreads();
        incl += t;
        sh[tid] = incl;
        __syncthreads();
    }
    if (tid < nblocks) g_blk_sum[tid] = incl - v;
}

__global__ __launch_bounds__(256)
void scan_add_kernel(int N, int E)
{
    const int i = blockIdx.x * 256 + threadIdx.x;
    if (i < N) {
        int rs = g_row_start[i] + g_blk_sum[blockIdx.x];
        g_row_start[i] = rs;
        g_cursor[i]    = rs;
    }
    if (i == 0) g_row_start[N] = E;
}

// fill: 2 edges per thread for MLP
__global__ void fill_kernel(const int*   __restrict__ rows,
                            const int*   __restrict__ cols,
                            const float* __restrict__ vals,
                            int E)
{
    int i2 = (blockIdx.x * blockDim.x + threadIdx.x) * 2;
    if (i2 + 1 < E) {
        const int2   r = *(const int2*)(rows + i2);
        const int2   c = *(const int2*)(cols + i2);
        const float2 v = *(const float2*)(vals + i2);
        int p0 = atomicAdd(&g_cursor[r.x], 1);
        int p1 = atomicAdd(&g_cursor[r.y], 1);
        g_edges[p0] = make_uint2((unsigned)c.x, __float_as_uint(v.x));
        g_edges[p1] = make_uint2((unsigned)c.y, __float_as_uint(v.y));
    } else if (i2 < E) {
        int pos = atomicAdd(&g_cursor[rows[i2]], 1);
        g_edges[pos] = make_uint2((unsigned)cols[i2], __float_as_uint(vals[i2]));
    }
}

// ---------------------------------------------------------------------------
// Kernel 5: row-parallel SpMM + bias + ReLU (one warp per output row)
// ---------------------------------------------------------------------------
__global__ __launch_bounds__(256)
void spmm_csr_kernel(const float* __restrict__ b,
                     float*       __restrict__ out,
                     int N)
{
    const int warp_in_blk = threadIdx.x >> 5;
    const int lane = threadIdx.x & 31;
    const int row  = blockIdx.x * 8 + warp_in_blk;
    if (row >= N) return;

    const int s = g_row_start[row];
    const int e = g_row_start[row + 1];

    float4 acc = make_float4(0.f, 0.f, 0.f, 0.f);

    int j = s;
    for (; j + 4 <= e; j += 4) {
        const uint2 e0 = g_edges[j];
        const uint2 e1 = g_edges[j + 1];
        const uint2 e2 = g_edges[j + 2];
        const uint2 e3 = g_edges[j + 3];
        const float4 a0 = __ldg((const float4*)(g_x + (size_t)e0.x * F_OUT) + lane);
        const float4 a1 = __ldg((const float4*)(g_x + (size_t)e1.x * F_OUT) + lane);
        const float4 a2 = __ldg((const float4*)(g_x + (size_t)e2.x * F_OUT) + lane);
        const float4 a3 = __ldg((const float4*)(g_x + (size_t)e3.x * F_OUT) + lane);
        const float v0 = __uint_as_float(e0.y);
        const float v1 = __uint_as_float(e1.y);
        const float v2 = __uint_as_float(e2.y);
        const float v3 = __uint_as_float(e3.y);
        acc.x = fmaf(v0, a0.x, acc.x); acc.y = fmaf(v0, a0.y, acc.y);
        acc.z = fmaf(v0, a0.z, acc.z); acc.w = fmaf(v0, a0.w, acc.w);
        acc.x = fmaf(v1, a1.x, acc.x); acc.y = fmaf(v1, a1.y, acc.y);
        acc.z = fmaf(v1, a1.z, acc.z); acc.w = fmaf(v1, a1.w, acc.w);
        acc.x = fmaf(v2, a2.x, acc.x); acc.y = fmaf(v2, a2.y, acc.y);
        acc.z = fmaf(v2, a2.z, acc.z); acc.w = fmaf(v2, a2.w, acc.w);
        acc.x = fmaf(v3, a3.x, acc.x); acc.y = fmaf(v3, a3.y, acc.y);
        acc.z = fmaf(v3, a3.z, acc.z); acc.w = fmaf(v3, a3.w, acc.w);
    }
    for (; j < e; j++) {
        const uint2 e0 = g_edges[j];
        const float4 a0 = __ldg((const float4*)(g_x + (size_t)e0.x * F_OUT) + lane);
        const float v0 = __uint_as_float(e0.y);
        acc.x = fmaf(v0, a0.x, acc.x); acc.y = fmaf(v0, a0.y, acc.y);
        acc.z = fmaf(v0, a0.z, acc.z); acc.w = fmaf(v0, a0.w, acc.w);
    }

    const float4 bb = ((const float4*)b)[lane];
    float4 r;
    r.x = fmaxf(acc.x + bb.x, 0.f);
    r.y = fmaxf(acc.y + bb.y, 0.f);
    r.z = fmaxf(acc.z + bb.z, 0.f);
    r.w = fmaxf(acc.w + bb.w, 0.f);
    ((float4*)(out + (size_t)row * F_OUT))[lane] = r;
}

// ---------------------------------------------------------------------------
extern "C" void kernel_launch(void* const* d_in, const int* in_sizes, int n_in,
                              void* d_out, int out_size)
{
    const float* features  = (const float*)d_in[0];  // [N, 512]
    const float* drop_mask = (const float*)d_in[1];  // [N, 512]
    const float* W         = (const float*)d_in[2];  // [512, 128]
    const float* b         = (const float*)d_in[3];  // [128]
    const int*   adj_rows  = (const int*)d_in[4];    // [E]
    const int*   adj_cols  = (const int*)d_in[5];    // [E]
    const float* adj_vals  = (const float*)d_in[6];  // [E]
    float* out = (float*)d_out;                      // [N, 128]

    const int M = in_sizes[0] / F_IN;
    const int E = in_sizes[4];
    const int nscan = (M + 255) / 256;

    // 0) split W once
    w_split_kernel<<<(F_IN * F_OUT + 255) / 256, 256>>>(W);

    // 1) x = (features * drop_mask) @ W   (split-bf16 tensor cores)
    gemm_dropout_mma_kernel<<<(M + BM - 1) / BM, 256>>>(features, drop_mask, M);

    // 2) CSR build (parallel 3-phase scan)
    zero_deg_kernel<<<(M + 255) / 256, 256>>>(M);
    hist_kernel<<<(E / 4 + 255) / 256, 256>>>(adj_rows, E);
    scan_blocks_kernel<<<nscan, 256>>>(M);
    scan_top_kernel<<<1, 512>>>(nscan);
    scan_add_kernel<<<nscan, 256>>>(M, E);
    fill_kernel<<<(E / 2 + 255) / 256, 256>>>(adj_rows, adj_cols, adj_vals, E);

    // 3) row-parallel SpMM + bias + ReLU
    spmm_csr_kernel<<<(M + 7) / 8, 256>>>(b, out, M);
}

// round 8
// speedup vs baseline: 1.4074x; 1.0955x over previous
#include <cuda_runtime.h>
#include <cuda_bf16.h>
#include <cstdint>

// Problem constants (fixed by the dataset)
#define F_IN   512
#define F_OUT  128
#define MAX_N  50048
#define MAX_E  1700000

// Scratch for x = (features * drop_mask) @ W   [N, F_OUT]
__device__ float g_x[(size_t)MAX_N * F_OUT];

// CSR scratch
__device__ int   g_deg[MAX_N];
__device__ int   g_row_start[MAX_N + 1];
__device__ int   g_cursor[MAX_N];
__device__ int   g_blk_sum[512];
__device__ uint2 g_edges[MAX_E];   // .x = col, .y = bits(val)

// ---------------------------------------------------------------------------
// MMA helpers
// ---------------------------------------------------------------------------
#define BM 128
#define BK 32
#define LDA 40    // As row length (bf16) with +8 pad: conflict-free ldmatrix
#define LDB 136   // Ws row length (bf16) with +8 pad

__device__ __forceinline__ void ldm_x4(uint32_t* f, uint32_t addr)
{
    asm volatile("ldmatrix.sync.aligned.m8n8.x4.shared.b16 {%0,%1,%2,%3}, [%4];"
                 : "=r"(f[0]), "=r"(f[1]), "=r"(f[2]), "=r"(f[3]) : "r"(addr));
}

__device__ __forceinline__ void ldm_x4_trans(uint32_t* f, uint32_t addr)
{
    asm volatile("ldmatrix.sync.aligned.m8n8.x4.trans.shared.b16 {%0,%1,%2,%3}, [%4];"
                 : "=r"(f[0]), "=r"(f[1]), "=r"(f[2]), "=r"(f[3]) : "r"(addr));
}

__device__ __forceinline__ void mma_bf16(float* c, const uint32_t* a,
                                         uint32_t b0, uint32_t b1)
{
    asm volatile(
        "mma.sync.aligned.m16n8k16.row.col.f32.bf16.bf16.f32 "
        "{%0,%1,%2,%3}, {%4,%5,%6,%7}, {%8,%9}, {%0,%1,%2,%3};"
        : "+f"(c[0]), "+f"(c[1]), "+f"(c[2]), "+f"(c[3])
        : "r"(a[0]), "r"(a[1]), "r"(a[2]), "r"(a[3]), "r"(b0), "r"(b1));
}

__device__ __forceinline__ uint32_t smem_u32(const void* p)
{
    uint32_t r;
    asm("{.reg .u64 t; cvta.to.shared.u64 t, %1; cvt.u32.u64 %0, t;}"
        : "=r"(r) : "l"(p));
    return r;
}

__device__ __forceinline__ uint32_t pack_bf16x2(float lo_val, float hi_val)
{
    __nv_bfloat162 h = __floats2bfloat162_rn(lo_val, hi_val);
    return *(uint32_t*)&h;
}

// ---------------------------------------------------------------------------
// Kernel 1: fused dropout + split-bf16 tensor-core GEMM  (R5 exact)
// x ~= Ah*Wh + Ah*Wl + Al*Wh  (fp32 accum; err ~1e-5)
// ---------------------------------------------------------------------------
__global__ __launch_bounds__(256)
void gemm_dropout_mma_kernel(const float* __restrict__ A,
                             const float* __restrict__ Mk,
                             const float* __restrict__ W,
                             int M)
{
    __shared__ __nv_bfloat16 As_hi[BM][LDA];
    __shared__ __nv_bfloat16 As_lo[BM][LDA];
    __shared__ __nv_bfloat16 Ws_hi[BK][LDB];
    __shared__ __nv_bfloat16 Ws_lo[BK][LDB];

    const int tid  = threadIdx.x;
    const int warp = tid >> 5;
    const int lane = tid & 31;
    const int block_m = blockIdx.x * BM;

    const int wm = (warp & 3) * 32;   // warp m-offset (0,32,64,96)
    const int wn = (warp >> 2) * 64;  // warp n-offset (0,64)

    const int aRow = lane & 15;
    const int aOff = (lane >> 4) * 8;

    float acc[2][8][4];
#pragma unroll
    for (int mt = 0; mt < 2; mt++)
#pragma unroll
        for (int nt = 0; nt < 8; nt++)
#pragma unroll
            for (int q = 0; q < 4; q++) acc[mt][nt][q] = 0.f;

    const uint32_t as_hi_b = smem_u32(&As_hi[0][0]);
    const uint32_t as_lo_b = smem_u32(&As_lo[0][0]);
    const uint32_t ws_hi_b = smem_u32(&Ws_hi[0][0]);
    const uint32_t ws_lo_b = smem_u32(&Ws_lo[0][0]);

    for (int k0 = 0; k0 < F_IN; k0 += BK) {
        // ---- fill A tiles: 128x32 fp32, fused dropout, split to hi/lo ----
#pragma unroll
        for (int p = 0; p < 4; p++) {
            int idx = p * 256 + tid;
            int row = idx >> 3;            // 0..127
            int col = (idx & 7) * 4;       // 0..28
            int gm  = block_m + row;
            float4 e = make_float4(0.f, 0.f, 0.f, 0.f);
            if (gm < M) {
                const float4 a = *(const float4*)(A  + (size_t)gm * F_IN + k0 + col);
                const float4 m = *(const float4*)(Mk + (size_t)gm * F_IN + k0 + col);
                e = make_float4(a.x * m.x, a.y * m.y, a.z * m.z, a.w * m.w);
            }
            float eh[4], el[4];
            const float ev[4] = {e.x, e.y, e.z, e.w};
#pragma unroll
            for (int q = 0; q < 4; q++) {
                __nv_bfloat16 h = __float2bfloat16(ev[q]);
                eh[q] = __bfloat162float(h);
                el[q] = ev[q] - eh[q];
            }
            uint2 hw, lw;
            hw.x = pack_bf16x2(eh[0], eh[1]); hw.y = pack_bf16x2(eh[2], eh[3]);
            lw.x = pack_bf16x2(el[0], el[1]); lw.y = pack_bf16x2(el[2], el[3]);
            *(uint2*)&As_hi[row][col] = hw;
            *(uint2*)&As_lo[row][col] = lw;
        }
        // ---- fill W tiles: 32x128 fp32, split to hi/lo (R5 in-loop path) ----
#pragma unroll
        for (int p = 0; p < 4; p++) {
            int idx = p * 256 + tid;
            int row = idx >> 5;            // 0..31
            int col = (idx & 31) * 4;      // 0..124
            const float4 w = *(const float4*)(W + (size_t)(k0 + row) * F_OUT + col);
            float eh[4], el[4];
            const float wv[4] = {w.x, w.y, w.z, w.w};
#pragma unroll
            for (int q = 0; q < 4; q++) {
                __nv_bfloat16 h = __float2bfloat16(wv[q]);
                eh[q] = __bfloat162float(h);
                el[q] = wv[q] - eh[q];
            }
            uint2 hw, lw;
            hw.x = pack_bf16x2(eh[0], eh[1]); hw.y = pack_bf16x2(eh[2], eh[3]);
            lw.x = pack_bf16x2(el[0], el[1]); lw.y = pack_bf16x2(el[2], el[3]);
            *(uint2*)&Ws_hi[row][col] = hw;
            *(uint2*)&Ws_lo[row][col] = lw;
        }
        __syncthreads();

        // ---- compute: two k16 steps per chunk ----
#pragma unroll
        for (int k16 = 0; k16 < BK; k16 += 16) {
            uint32_t ah[2][4], al[2][4];
#pragma unroll
            for (int mt = 0; mt < 2; mt++) {
                int r = wm + mt * 16 + aRow;
                int c = k16 + aOff;
                ldm_x4(ah[mt], as_hi_b + (uint32_t)(r * LDA + c) * 2);
                ldm_x4(al[mt], as_lo_b + (uint32_t)(r * LDA + c) * 2);
            }
            uint32_t bh[4][4], bl[4][4];
#pragma unroll
            for (int nq = 0; nq < 4; nq++) {
                int kr = k16 + (lane & 15);
                int c  = wn + nq * 16 + aOff;
                ldm_x4_trans(bh[nq], ws_hi_b + (uint32_t)(kr * LDB + c) * 2);
                ldm_x4_trans(bl[nq], ws_lo_b + (uint32_t)(kr * LDB + c) * 2);
            }
#pragma unroll
            for (int mt = 0; mt < 2; mt++) {
#pragma unroll
                for (int nt = 0; nt < 8; nt++) {
                    const int nq = nt >> 1, pr = (nt & 1) * 2;
                    mma_bf16(acc[mt][nt], ah[mt], bh[nq][pr], bh[nq][pr + 1]);
                    mma_bf16(acc[mt][nt], ah[mt], bl[nq][pr], bl[nq][pr + 1]);
                    mma_bf16(acc[mt][nt], al[mt], bh[nq][pr], bh[nq][pr + 1]);
                }
            }
        }
        __syncthreads();
    }

    // ---- store x tile ----
    const int gid = lane >> 2;
    const int tq  = lane & 3;
#pragma unroll
    for (int mt = 0; mt < 2; mt++) {
        int gm0 = block_m + wm + mt * 16 + gid;
        int gm1 = gm0 + 8;
#pragma unroll
        for (int nt = 0; nt < 8; nt++) {
            int col = wn + nt * 8 + tq * 2;
            if (gm0 < M)
                *(float2*)(g_x + (size_t)gm0 * F_OUT + col) =
                    make_float2(acc[mt][nt][0], acc[mt][nt][1]);
            if (gm1 < M)
                *(float2*)(g_x + (size_t)gm1 * F_OUT + col) =
                    make_float2(acc[mt][nt][2], acc[mt][nt][3]);
        }
    }
}

// ---------------------------------------------------------------------------
// CSR build
// ---------------------------------------------------------------------------
__global__ void zero_deg_kernel(int N)
{
    int i = blockIdx.x * blockDim.x + threadIdx.x;
    if (i < N) g_deg[i] = 0;
}

// hist: 4 edges per thread (int4) for MLP
__global__ void hist_kernel(const int* __restrict__ rows, int E)
{
    int i4 = (blockIdx.x * blockDim.x + threadIdx.x) * 4;
    if (i4 + 3 < E) {
        const int4 r = *(const int4*)(rows + i4);
        atomicAdd(&g_deg[r.x], 1);
        atomicAdd(&g_deg[r.y], 1);
        atomicAdd(&g_deg[r.z], 1);
        atomicAdd(&g_deg[r.w], 1);
    } else {
        for (int i = i4; i < E; i++) atomicAdd(&g_deg[rows[i]], 1);
    }
}

__global__ __launch_bounds__(256)
void scan_blocks_kernel(int N)
{
    __shared__ int sh[256];
    const int tid = threadIdx.x;
    const int i = blockIdx.x * 256 + tid;

    int v = (i < N) ? g_deg[i] : 0;
    int incl = v;
    sh[tid] = incl;
    __syncthreads();
#pragma unroll
    for (int off = 1; off < 256; off <<= 1) {
        int t = (tid >= off) ? sh[tid - off] : 0;
        __syncthreads();
        incl += t;
        sh[tid] = incl;
        __syncthreads();
    }
    if (i < N) g_row_start[i] = incl - v;
    if (tid == 255) g_blk_sum[blockIdx.x] = incl;
}

__global__ __launch_bounds__(512)
void scan_top_kernel(int nblocks)
{
    __shared__ int sh[512];
    const int tid = threadIdx.x;
    int v = (tid < nblocks) ? g_blk_sum[tid] : 0;
    int incl = v;
    sh[tid] = incl;
    __syncthreads();
#pragma unroll
    for (int off = 1; off < 512; off <<= 1) {
        int t = (tid >= off) ? sh[tid - off] : 0;
        __syncthreads();
        incl += t;
        sh[tid] = incl;
        __syncthreads();
    }
    if (tid < nblocks) g_blk_sum[tid] = incl - v;
}

__global__ __launch_bounds__(256)
void scan_add_kernel(int N, int E)
{
    const int i = blockIdx.x * 256 + threadIdx.x;
    if (i < N) {
        int rs = g_row_start[i] + g_blk_sum[blockIdx.x];
        g_row_start[i] = rs;
        g_cursor[i]    = rs;
    }
    if (i == 0) g_row_start[N] = E;
}

// fill: 2 edges per thread for MLP
__global__ void fill_kernel(const int*   __restrict__ rows,
                            const int*   __restrict__ cols,
                            const float* __restrict__ vals,
                            int E)
{
    int i2 = (blockIdx.x * blockDim.x + threadIdx.x) * 2;
    if (i2 + 1 < E) {
        const int2   r = *(const int2*)(rows + i2);
        const int2   c = *(const int2*)(cols + i2);
        const float2 v = *(const float2*)(vals + i2);
        int p0 = atomicAdd(&g_cursor[r.x], 1);
        int p1 = atomicAdd(&g_cursor[r.y], 1);
        g_edges[p0] = make_uint2((unsigned)c.x, __float_as_uint(v.x));
        g_edges[p1] = make_uint2((unsigned)c.y, __float_as_uint(v.y));
    } else if (i2 < E) {
        int pos = atomicAdd(&g_cursor[rows[i2]], 1);
        g_edges[pos] = make_uint2((unsigned)cols[i2], __float_as_uint(vals[i2]));
    }
}

// ---------------------------------------------------------------------------
// Kernel 5: row-parallel SpMM + bias + ReLU (one warp per output row)
// ---------------------------------------------------------------------------
__global__ __launch_bounds__(256)
void spmm_csr_kernel(const float* __restrict__ b,
                     float*       __restrict__ out,
                     int N)
{
    const int warp_in_blk = threadIdx.x >> 5;
    const int lane = threadIdx.x & 31;
    const int row  = blockIdx.x * 8 + warp_in_blk;
    if (row >= N) return;

    const int s = g_row_start[row];
    const int e = g_row_start[row + 1];

    float4 acc = make_float4(0.f, 0.f, 0.f, 0.f);

    int j = s;
    for (; j + 4 <= e; j += 4) {
        const uint2 e0 = g_edges[j];
        const uint2 e1 = g_edges[j + 1];
        const uint2 e2 = g_edges[j + 2];
        const uint2 e3 = g_edges[j + 3];
        const float4 a0 = __ldg((const float4*)(g_x + (size_t)e0.x * F_OUT) + lane);
        const float4 a1 = __ldg((const float4*)(g_x + (size_t)e1.x * F_OUT) + lane);
        const float4 a2 = __ldg((const float4*)(g_x + (size_t)e2.x * F_OUT) + lane);
        const float4 a3 = __ldg((const float4*)(g_x + (size_t)e3.x * F_OUT) + lane);
        const float v0 = __uint_as_float(e0.y);
        const float v1 = __uint_as_float(e1.y);
        const float v2 = __uint_as_float(e2.y);
        const float v3 = __uint_as_float(e3.y);
        acc.x = fmaf(v0, a0.x, acc.x); acc.y = fmaf(v0, a0.y, acc.y);
        acc.z = fmaf(v0, a0.z, acc.z); acc.w = fmaf(v0, a0.w, acc.w);
        acc.x = fmaf(v1, a1.x, acc.x); acc.y = fmaf(v1, a1.y, acc.y);
        acc.z = fmaf(v1, a1.z, acc.z); acc.w = fmaf(v1, a1.w, acc.w);
        acc.x = fmaf(v2, a2.x, acc.x); acc.y = fmaf(v2, a2.y, acc.y);
        acc.z = fmaf(v2, a2.z, acc.z); acc.w = fmaf(v2, a2.w, acc.w);
        acc.x = fmaf(v3, a3.x, acc.x); acc.y = fmaf(v3, a3.y, acc.y);
        acc.z = fmaf(v3, a3.z, acc.z); acc.w = fmaf(v3, a3.w, acc.w);
    }
    for (; j < e; j++) {
        const uint2 e0 = g_edges[j];
        const float4 a0 = __ldg((const float4*)(g_x + (size_t)e0.x * F_OUT) + lane);
        const float v0 = __uint_as_float(e0.y);
        acc.x = fmaf(v0, a0.x, acc.x); acc.y = fmaf(v0, a0.y, acc.y);
        acc.z = fmaf(v0, a0.z, acc.z); acc.w = fmaf(v0, a0.w, acc.w);
    }

    const float4 bb = ((const float4*)b)[lane];
    float4 r;
    r.x = fmaxf(acc.x + bb.x, 0.f);
    r.y = fmaxf(acc.y + bb.y, 0.f);
    r.z = fmaxf(acc.z + bb.z, 0.f);
    r.w = fmaxf(acc.w + bb.w, 0.f);
    ((float4*)(out + (size_t)row * F_OUT))[lane] = r;
}

// ---------------------------------------------------------------------------
extern "C" void kernel_launch(void* const* d_in, const int* in_sizes, int n_in,
                              void* d_out, int out_size)
{
    const float* features  = (const float*)d_in[0];  // [N, 512]
    const float* drop_mask = (const float*)d_in[1];  // [N, 512]
    const float* W         = (const float*)d_in[2];  // [512, 128]
    const float* b         = (const float*)d_in[3];  // [128]
    const int*   adj_rows  = (const int*)d_in[4];    // [E]
    const int*   adj_cols  = (const int*)d_in[5];    // [E]
    const float* adj_vals  = (const float*)d_in[6];  // [E]
    float* out = (float*)d_out;                      // [N, 128]

    const int M = in_sizes[0] / F_IN;
    const int E = in_sizes[4];
    const int nscan = (M + 255) / 256;

    // 1) x = (features * drop_mask) @ W   (split-bf16 tensor cores, R5 exact)
    gemm_dropout_mma_kernel<<<(M + BM - 1) / BM, 256>>>(features, drop_mask, W, M);

    // 2) CSR build (parallel 3-phase scan; vectorized hist/fill)
    zero_deg_kernel<<<(M + 255) / 256, 256>>>(M);
    hist_kernel<<<(E / 4 + 255) / 256, 256>>>(adj_rows, E);
    scan_blocks_kernel<<<nscan, 256>>>(M);
    scan_top_kernel<<<1, 512>>>(nscan);
    scan_add_kernel<<<nscan, 256>>>(M, E);
    fill_kernel<<<(E / 2 + 255) / 256, 256>>>(adj_rows, adj_cols, adj_vals, E);

    // 3) row-parallel SpMM + bias + ReLU
    spmm_csr_kernel<<<(M + 7) / 8, 256>>>(b, out, M);
}

// round 9
// speedup vs baseline: 1.6039x; 1.1396x over previous
#include <cuda_runtime.h>
#include <cuda_bf16.h>
#include <cstdint>

// Problem constants (fixed by the dataset)
#define F_IN   512
#define F_OUT  128
#define MAX_N  50048
#define MAX_E  1700000

// Scratch for x = (features * drop_mask) @ W   [N, F_OUT]
__device__ float g_x[(size_t)MAX_N * F_OUT];

// CSR scratch
__device__ int   g_deg[MAX_N];
__device__ int   g_row_start[MAX_N + 1];
__device__ int   g_cursor[MAX_N];
__device__ int   g_blk_sum[512];
__device__ uint2 g_edges[MAX_E];   // .x = col, .y = bits(val)

// ---------------------------------------------------------------------------
// MMA helpers
// ---------------------------------------------------------------------------
#define BM 128
#define BK 32
#define LDA 40    // As row length (bf16) with +8 pad: conflict-free ldmatrix
#define LDB 136   // Ws row length (bf16) with +8 pad

__device__ __forceinline__ void ldm_x4(uint32_t* f, uint32_t addr)
{
    asm volatile("ldmatrix.sync.aligned.m8n8.x4.shared.b16 {%0,%1,%2,%3}, [%4];"
                 : "=r"(f[0]), "=r"(f[1]), "=r"(f[2]), "=r"(f[3]) : "r"(addr));
}

__device__ __forceinline__ void ldm_x4_trans(uint32_t* f, uint32_t addr)
{
    asm volatile("ldmatrix.sync.aligned.m8n8.x4.trans.shared.b16 {%0,%1,%2,%3}, [%4];"
                 : "=r"(f[0]), "=r"(f[1]), "=r"(f[2]), "=r"(f[3]) : "r"(addr));
}

__device__ __forceinline__ void mma_bf16(float* c, const uint32_t* a,
                                         uint32_t b0, uint32_t b1)
{
    asm volatile(
        "mma.sync.aligned.m16n8k16.row.col.f32.bf16.bf16.f32 "
        "{%0,%1,%2,%3}, {%4,%5,%6,%7}, {%8,%9}, {%0,%1,%2,%3};"
        : "+f"(c[0]), "+f"(c[1]), "+f"(c[2]), "+f"(c[3])
        : "r"(a[0]), "r"(a[1]), "r"(a[2]), "r"(a[3]), "r"(b0), "r"(b1));
}

__device__ __forceinline__ uint32_t smem_u32(const void* p)
{
    uint32_t r;
    asm("{.reg .u64 t; cvta.to.shared.u64 t, %1; cvt.u32.u64 %0, t;}"
        : "=r"(r) : "l"(p));
    return r;
}

__device__ __forceinline__ uint32_t pack_bf16x2(float lo_val, float hi_val)
{
    __nv_bfloat162 h = __floats2bfloat162_rn(lo_val, hi_val);
    return *(uint32_t*)&h;
}

// ---------------------------------------------------------------------------
// Kernel 1: fused dropout + split-bf16 tensor-core GEMM  (R5 exact)
// x ~= Ah*Wh + Ah*Wl + Al*Wh  (fp32 accum; err ~1e-5)
// ---------------------------------------------------------------------------
__global__ __launch_bounds__(256)
void gemm_dropout_mma_kernel(const float* __restrict__ A,
                             const float* __restrict__ Mk,
                             const float* __restrict__ W,
                             int M)
{
    __shared__ __nv_bfloat16 As_hi[BM][LDA];
    __shared__ __nv_bfloat16 As_lo[BM][LDA];
    __shared__ __nv_bfloat16 Ws_hi[BK][LDB];
    __shared__ __nv_bfloat16 Ws_lo[BK][LDB];

    const int tid  = threadIdx.x;
    const int warp = tid >> 5;
    const int lane = tid & 31;
    const int block_m = blockIdx.x * BM;

    const int wm = (warp & 3) * 32;   // warp m-offset (0,32,64,96)
    const int wn = (warp >> 2) * 64;  // warp n-offset (0,64)

    const int aRow = lane & 15;
    const int aOff = (lane >> 4) * 8;

    float acc[2][8][4];
#pragma unroll
    for (int mt = 0; mt < 2; mt++)
#pragma unroll
        for (int nt = 0; nt < 8; nt++)
#pragma unroll
            for (int q = 0; q < 4; q++) acc[mt][nt][q] = 0.f;

    const uint32_t as_hi_b = smem_u32(&As_hi[0][0]);
    const uint32_t as_lo_b = smem_u32(&As_lo[0][0]);
    const uint32_t ws_hi_b = smem_u32(&Ws_hi[0][0]);
    const uint32_t ws_lo_b = smem_u32(&Ws_lo[0][0]);

    for (int k0 = 0; k0 < F_IN; k0 += BK) {
        // ---- fill A tiles: 128x32 fp32, fused dropout, split to hi/lo ----
#pragma unroll
        for (int p = 0; p < 4; p++) {
            int idx = p * 256 + tid;
            int row = idx >> 3;            // 0..127
            int col = (idx & 7) * 4;       // 0..28
            int gm  = block_m + row;
            float4 e = make_float4(0.f, 0.f, 0.f, 0.f);
            if (gm < M) {
                const float4 a = *(const float4*)(A  + (size_t)gm * F_IN + k0 + col);
                const float4 m = *(const float4*)(Mk + (size_t)gm * F_IN + k0 + col);
                e = make_float4(a.x * m.x, a.y * m.y, a.z * m.z, a.w * m.w);
            }
            float eh[4], el[4];
            const float ev[4] = {e.x, e.y, e.z, e.w};
#pragma unroll
            for (int q = 0; q < 4; q++) {
                __nv_bfloat16 h = __float2bfloat16(ev[q]);
                eh[q] = __bfloat162float(h);
                el[q] = ev[q] - eh[q];
            }
            uint2 hw, lw;
            hw.x = pack_bf16x2(eh[0], eh[1]); hw.y = pack_bf16x2(eh[2], eh[3]);
            lw.x = pack_bf16x2(el[0], el[1]); lw.y = pack_bf16x2(el[2], el[3]);
            *(uint2*)&As_hi[row][col] = hw;
            *(uint2*)&As_lo[row][col] = lw;
        }
        // ---- fill W tiles: 32x128 fp32, split to hi/lo ----
#pragma unroll
        for (int p = 0; p < 4; p++) {
            int idx = p * 256 + tid;
            int row = idx >> 5;            // 0..31
            int col = (idx & 31) * 4;      // 0..124
            const float4 w = *(const float4*)(W + (size_t)(k0 + row) * F_OUT + col);
            float eh[4], el[4];
            const float wv[4] = {w.x, w.y, w.z, w.w};
#pragma unroll
            for (int q = 0; q < 4; q++) {
                __nv_bfloat16 h = __float2bfloat16(wv[q]);
                eh[q] = __bfloat162float(h);
                el[q] = wv[q] - eh[q];
            }
            uint2 hw, lw;
            hw.x = pack_bf16x2(eh[0], eh[1]); hw.y = pack_bf16x2(eh[2], eh[3]);
            lw.x = pack_bf16x2(el[0], el[1]); lw.y = pack_bf16x2(el[2], el[3]);
            *(uint2*)&Ws_hi[row][col] = hw;
            *(uint2*)&Ws_lo[row][col] = lw;
        }
        __syncthreads();

        // ---- compute: two k16 steps per chunk ----
#pragma unroll
        for (int k16 = 0; k16 < BK; k16 += 16) {
            uint32_t ah[2][4], al[2][4];
#pragma unroll
            for (int mt = 0; mt < 2; mt++) {
                int r = wm + mt * 16 + aRow;
                int c = k16 + aOff;
                ldm_x4(ah[mt], as_hi_b + (uint32_t)(r * LDA + c) * 2);
                ldm_x4(al[mt], as_lo_b + (uint32_t)(r * LDA + c) * 2);
            }
            uint32_t bh[4][4], bl[4][4];
#pragma unroll
            for (int nq = 0; nq < 4; nq++) {
                int kr = k16 + (lane & 15);
                int c  = wn + nq * 16 + aOff;
                ldm_x4_trans(bh[nq], ws_hi_b + (uint32_t)(kr * LDB + c) * 2);
                ldm_x4_trans(bl[nq], ws_lo_b + (uint32_t)(kr * LDB + c) * 2);
            }
#pragma unroll
            for (int mt = 0; mt < 2; mt++) {
#pragma unroll
                for (int nt = 0; nt < 8; nt++) {
                    const int nq = nt >> 1, pr = (nt & 1) * 2;
                    mma_bf16(acc[mt][nt], ah[mt], bh[nq][pr], bh[nq][pr + 1]);
                    mma_bf16(acc[mt][nt], ah[mt], bl[nq][pr], bl[nq][pr + 1]);
                    mma_bf16(acc[mt][nt], al[mt], bh[nq][pr], bh[nq][pr + 1]);
                }
            }
        }
        __syncthreads();
    }

    // ---- store x tile ----
    const int gid = lane >> 2;
    const int tq  = lane & 3;
#pragma unroll
    for (int mt = 0; mt < 2; mt++) {
        int gm0 = block_m + wm + mt * 16 + gid;
        int gm1 = gm0 + 8;
#pragma unroll
        for (int nt = 0; nt < 8; nt++) {
            int col = wn + nt * 8 + tq * 2;
            if (gm0 < M)
                *(float2*)(g_x + (size_t)gm0 * F_OUT + col) =
                    make_float2(acc[mt][nt][0], acc[mt][nt][1]);
            if (gm1 < M)
                *(float2*)(g_x + (size_t)gm1 * F_OUT + col) =
                    make_float2(acc[mt][nt][2], acc[mt][nt][3]);
        }
    }
}

// ---------------------------------------------------------------------------
// CSR build
// ---------------------------------------------------------------------------
__global__ void zero_deg_kernel(int N)
{
    int i = blockIdx.x * blockDim.x + threadIdx.x;
    if (i < N) g_deg[i] = 0;
}

// hist: 4 edges per thread (int4) for MLP
__global__ void hist_kernel(const int* __restrict__ rows, int E)
{
    int i4 = (blockIdx.x * blockDim.x + threadIdx.x) * 4;
    if (i4 + 3 < E) {
        const int4 r = *(const int4*)(rows + i4);
        atomicAdd(&g_deg[r.x], 1);
        atomicAdd(&g_deg[r.y], 1);
        atomicAdd(&g_deg[r.z], 1);
        atomicAdd(&g_deg[r.w], 1);
    } else {
        for (int i = i4; i < E; i++) atomicAdd(&g_deg[rows[i]], 1);
    }
}

__global__ __launch_bounds__(256)
void scan_blocks_kernel(int N)
{
    __shared__ int sh[256];
    const int tid = threadIdx.x;
    const int i = blockIdx.x * 256 + tid;

    int v = (i < N) ? g_deg[i] : 0;
    int incl = v;
    sh[tid] = incl;
    __syncthreads();
#pragma unroll
    for (int off = 1; off < 256; off <<= 1) {
        int t = (tid >= off) ? sh[tid - off] : 0;
        __syncthreads();
        incl += t;
        sh[tid] = incl;
        __syncthreads();
    }
    if (i < N) g_row_start[i] = incl - v;
    if (tid == 255) g_blk_sum[blockIdx.x] = incl;
}

__global__ __launch_bounds__(512)
void scan_top_kernel(int nblocks)
{
    __shared__ int sh[512];
    const int tid = threadIdx.x;
    int v = (tid < nblocks) ? g_blk_sum[tid] : 0;
    int incl = v;
    sh[tid] = incl;
    __syncthreads();
#pragma unroll
    for (int off = 1; off < 512; off <<= 1) {
        int t = (tid >= off) ? sh[tid - off] : 0;
        __syncthreads();
        incl += t;
        sh[tid] = incl;
        __syncthreads();
    }
    if (tid < nblocks) g_blk_sum[tid] = incl - v;
}

__global__ __launch_bounds__(256)
void scan_add_kernel(int N, int E)
{
    const int i = blockIdx.x * 256 + threadIdx.x;
    if (i < N) {
        int rs = g_row_start[i] + g_blk_sum[blockIdx.x];
        g_row_start[i] = rs;
        g_cursor[i]    = rs;
    }
    if (i == 0) g_row_start[N] = E;
}

// fill: 2 edges per thread for MLP
__global__ void fill_kernel(const int*   __restrict__ rows,
                            const int*   __restrict__ cols,
                            const float* __restrict__ vals,
                            int E)
{
    int i2 = (blockIdx.x * blockDim.x + threadIdx.x) * 2;
    if (i2 + 1 < E) {
        const int2   r = *(const int2*)(rows + i2);
        const int2   c = *(const int2*)(cols + i2);
        const float2 v = *(const float2*)(vals + i2);
        int p0 = atomicAdd(&g_cursor[r.x], 1);
        int p1 = atomicAdd(&g_cursor[r.y], 1);
        g_edges[p0] = make_uint2((unsigned)c.x, __float_as_uint(v.x));
        g_edges[p1] = make_uint2((unsigned)c.y, __float_as_uint(v.y));
    } else if (i2 < E) {
        int pos = atomicAdd(&g_cursor[rows[i2]], 1);
        g_edges[pos] = make_uint2((unsigned)cols[i2], __float_as_uint(vals[i2]));
    }
}

// ---------------------------------------------------------------------------
// Kernel 5: row-parallel SpMM + bias + ReLU (one warp per output row)
// ---------------------------------------------------------------------------
__global__ __launch_bounds__(256)
void spmm_csr_kernel(const float* __restrict__ b,
                     float*       __restrict__ out,
                     int N)
{
    const int warp_in_blk = threadIdx.x >> 5;
    const int lane = threadIdx.x & 31;
    const int row  = blockIdx.x * 8 + warp_in_blk;
    if (row >= N) return;

    const int s = g_row_start[row];
    const int e = g_row_start[row + 1];

    float4 acc = make_float4(0.f, 0.f, 0.f, 0.f);

    int j = s;
    for (; j + 4 <= e; j += 4) {
        const uint2 e0 = g_edges[j];
        const uint2 e1 = g_edges[j + 1];
        const uint2 e2 = g_edges[j + 2];
        const uint2 e3 = g_edges[j + 3];
        const float4 a0 = __ldg((const float4*)(g_x + (size_t)e0.x * F_OUT) + lane);
        const float4 a1 = __ldg((const float4*)(g_x + (size_t)e1.x * F_OUT) + lane);
        const float4 a2 = __ldg((const float4*)(g_x + (size_t)e2.x * F_OUT) + lane);
        const float4 a3 = __ldg((const float4*)(g_x + (size_t)e3.x * F_OUT) + lane);
        const float v0 = __uint_as_float(e0.y);
        const float v1 = __uint_as_float(e1.y);
        const float v2 = __uint_as_float(e2.y);
        const float v3 = __uint_as_float(e3.y);
        acc.x = fmaf(v0, a0.x, acc.x); acc.y = fmaf(v0, a0.y, acc.y);
        acc.z = fmaf(v0, a0.z, acc.z); acc.w = fmaf(v0, a0.w, acc.w);
        acc.x = fmaf(v1, a1.x, acc.x); acc.y = fmaf(v1, a1.y, acc.y);
        acc.z = fmaf(v1, a1.z, acc.z); acc.w = fmaf(v1, a1.w, acc.w);
        acc.x = fmaf(v2, a2.x, acc.x); acc.y = fmaf(v2, a2.y, acc.y);
        acc.z = fmaf(v2, a2.z, acc.z); acc.w = fmaf(v2, a2.w, acc.w);
        acc.x = fmaf(v3, a3.x, acc.x); acc.y = fmaf(v3, a3.y, acc.y);
        acc.z = fmaf(v3, a3.z, acc.z); acc.w = fmaf(v3, a3.w, acc.w);
    }
    for (; j < e; j++) {
        const uint2 e0 = g_edges[j];
        const float4 a0 = __ldg((const float4*)(g_x + (size_t)e0.x * F_OUT) + lane);
        const float v0 = __uint_as_float(e0.y);
        acc.x = fmaf(v0, a0.x, acc.x); acc.y = fmaf(v0, a0.y, acc.y);
        acc.z = fmaf(v0, a0.z, acc.z); acc.w = fmaf(v0, a0.w, acc.w);
    }

    const float4 bb = ((const float4*)b)[lane];
    float4 r;
    r.x = fmaxf(acc.x + bb.x, 0.f);
    r.y = fmaxf(acc.y + bb.y, 0.f);
    r.z = fmaxf(acc.z + bb.z, 0.f);
    r.w = fmaxf(acc.w + bb.w, 0.f);
    ((float4*)(out + (size_t)row * F_OUT))[lane] = r;
}

// ---------------------------------------------------------------------------
extern "C" void kernel_launch(void* const* d_in, const int* in_sizes, int n_in,
                              void* d_out, int out_size)
{
    const float* features  = (const float*)d_in[0];  // [N, 512]
    const float* drop_mask = (const float*)d_in[1];  // [N, 512]
    const float* W         = (const float*)d_in[2];  // [512, 128]
    const float* b         = (const float*)d_in[3];  // [128]
    const int*   adj_rows  = (const int*)d_in[4];    // [E]
    const int*   adj_cols  = (const int*)d_in[5];    // [E]
    const float* adj_vals  = (const float*)d_in[6];  // [E]
    float* out = (float*)d_out;                      // [N, 128]

    const int M = in_sizes[0] / F_IN;
    const int E = in_sizes[4];
    const int nscan = (M + 255) / 256;

    // Fork a side stream for the CSR build so it overlaps the GEMM.
    // kernel_launch runs only a handful of times (correctness + capture);
    // the stream/events are intentionally not destroyed (capture-safe).
    cudaStream_t s2;
    cudaStreamCreateWithFlags(&s2, cudaStreamNonBlocking);
    cudaEvent_t evFork, evJoin;
    cudaEventCreateWithFlags(&evFork, cudaEventDisableTiming);
    cudaEventCreateWithFlags(&evJoin, cudaEventDisableTiming);

    // fork: s2 branches off the main (capture-origin) stream
    cudaEventRecord(evFork, 0);
    cudaStreamWaitEvent(s2, evFork, 0);

    // branch A (main stream): GEMM
    gemm_dropout_mma_kernel<<<(M + BM - 1) / BM, 256>>>(features, drop_mask, W, M);

    // branch B (s2): CSR build
    zero_deg_kernel<<<(M + 255) / 256, 256, 0, s2>>>(M);
    hist_kernel<<<(E / 4 + 255) / 256, 256, 0, s2>>>(adj_rows, E);
    scan_blocks_kernel<<<nscan, 256, 0, s2>>>(M);
    scan_top_kernel<<<1, 512, 0, s2>>>(nscan);
    scan_add_kernel<<<nscan, 256, 0, s2>>>(M, E);
    fill_kernel<<<(E / 2 + 255) / 256, 256, 0, s2>>>(adj_rows, adj_cols, adj_vals, E);

    // join: main stream waits for CSR build
    cudaEventRecord(evJoin, s2);
    cudaStreamWaitEvent(0, evJoin, 0);

    // SpMM + bias + ReLU (needs both branches)
    spmm_csr_kernel<<<(M + 7) / 8, 256>>>(b, out, M);
}

// round 10
// speedup vs baseline: 1.6123x; 1.0052x over previous
#include <cuda_runtime.h>
#include <cuda_bf16.h>
#include <cstdint>

// Problem constants (fixed by the dataset)
#define F_IN   512
#define F_OUT  128
#define MAX_N  50048
#define MAX_E  1700000

// Scratch for x = (features * drop_mask) @ W   [N, F_OUT]
__device__ float g_x[(size_t)MAX_N * F_OUT];

// CSR scratch
__device__ int   g_deg[MAX_N];
__device__ int   g_row_start[MAX_N + 1];
__device__ int   g_cursor[MAX_N];
__device__ int   g_blk_sum[512];
__device__ uint2 g_edges[MAX_E];   // .x = col, .y = bits(val)

// ---------------------------------------------------------------------------
// MMA helpers
// ---------------------------------------------------------------------------
#define BM 128
#define BK 32
#define LDA 40    // As row length (bf16) with +8 pad: conflict-free ldmatrix
#define LDB 136   // Ws row length (bf16) with +8 pad

__device__ __forceinline__ void ldm_x4(uint32_t* f, uint32_t addr)
{
    asm volatile("ldmatrix.sync.aligned.m8n8.x4.shared.b16 {%0,%1,%2,%3}, [%4];"
                 : "=r"(f[0]), "=r"(f[1]), "=r"(f[2]), "=r"(f[3]) : "r"(addr));
}

__device__ __forceinline__ void ldm_x4_trans(uint32_t* f, uint32_t addr)
{
    asm volatile("ldmatrix.sync.aligned.m8n8.x4.trans.shared.b16 {%0,%1,%2,%3}, [%4];"
                 : "=r"(f[0]), "=r"(f[1]), "=r"(f[2]), "=r"(f[3]) : "r"(addr));
}

__device__ __forceinline__ void mma_bf16(float* c, const uint32_t* a,
                                         uint32_t b0, uint32_t b1)
{
    asm volatile(
        "mma.sync.aligned.m16n8k16.row.col.f32.bf16.bf16.f32 "
        "{%0,%1,%2,%3}, {%4,%5,%6,%7}, {%8,%9}, {%0,%1,%2,%3};"
        : "+f"(c[0]), "+f"(c[1]), "+f"(c[2]), "+f"(c[3])
        : "r"(a[0]), "r"(a[1]), "r"(a[2]), "r"(a[3]), "r"(b0), "r"(b1));
}

__device__ __forceinline__ uint32_t smem_u32(const void* p)
{
    uint32_t r;
    asm("{.reg .u64 t; cvta.to.shared.u64 t, %1; cvt.u32.u64 %0, t;}"
        : "=r"(r) : "l"(p));
    return r;
}

__device__ __forceinline__ uint32_t pack_bf16x2(float lo_val, float hi_val)
{
    __nv_bfloat162 h = __floats2bfloat162_rn(lo_val, hi_val);
    return *(uint32_t*)&h;
}

// split one float4 into bf16 hi/lo packed pairs and store to smem
__device__ __forceinline__ void split_store(const float4 e,
                                            __nv_bfloat16* hi_dst,
                                            __nv_bfloat16* lo_dst)
{
    float eh[4], el[4];
    const float ev[4] = {e.x, e.y, e.z, e.w};
#pragma unroll
    for (int q = 0; q < 4; q++) {
        __nv_bfloat16 h = __float2bfloat16(ev[q]);
        eh[q] = __bfloat162float(h);
        el[q] = ev[q] - eh[q];
    }
    uint2 hw, lw;
    hw.x = pack_bf16x2(eh[0], eh[1]); hw.y = pack_bf16x2(eh[2], eh[3]);
    lw.x = pack_bf16x2(el[0], el[1]); lw.y = pack_bf16x2(el[2], el[3]);
    *(uint2*)hi_dst = hw;
    *(uint2*)lo_dst = lw;
}

// ---------------------------------------------------------------------------
// Kernel 1: fused dropout + split-bf16 tensor-core GEMM
// Register-staged double buffering: chunk k+1's global loads are issued
// before chunk k's MMA phase, hiding the DRAM latency of A/mask.
// ---------------------------------------------------------------------------
__global__ __launch_bounds__(256)
void gemm_dropout_mma_kernel(const float* __restrict__ A,
                             const float* __restrict__ Mk,
                             const float* __restrict__ W,
                             int M)
{
    __shared__ __nv_bfloat16 As_hi[BM][LDA];
    __shared__ __nv_bfloat16 As_lo[BM][LDA];
    __shared__ __nv_bfloat16 Ws_hi[BK][LDB];
    __shared__ __nv_bfloat16 Ws_lo[BK][LDB];

    const int tid  = threadIdx.x;
    const int warp = tid >> 5;
    const int lane = tid & 31;
    const int block_m = blockIdx.x * BM;

    const int wm = (warp & 3) * 32;   // warp m-offset (0,32,64,96)
    const int wn = (warp >> 2) * 64;  // warp n-offset (0,64)

    const int aRow = lane & 15;
    const int aOff = (lane >> 4) * 8;

    // per-thread fill geometry (constant across chunks)
    const int a_row  = tid >> 3;           // with p*32 added per iter: rows 0..127
    const int a_col  = (tid & 7) * 4;      // 0..28
    const int w_row  = tid >> 5;           // with p*8 added: rows 0..31
    const int w_col  = (tid & 31) * 4;     // 0..124

    float acc[2][8][4];
#pragma unroll
    for (int mt = 0; mt < 2; mt++)
#pragma unroll
        for (int nt = 0; nt < 8; nt++)
#pragma unroll
            for (int q = 0; q < 4; q++) acc[mt][nt][q] = 0.f;

    const uint32_t as_hi_b = smem_u32(&As_hi[0][0]);
    const uint32_t as_lo_b = smem_u32(&As_lo[0][0]);
    const uint32_t ws_hi_b = smem_u32(&Ws_hi[0][0]);
    const uint32_t ws_lo_b = smem_u32(&Ws_lo[0][0]);

    // ---- prologue: load chunk 0 into registers ----
    float4 eA[4];   // A .* mask, staged
    float4 wV[4];   // W, staged
#pragma unroll
    for (int p = 0; p < 4; p++) {
        int gm = block_m + a_row + p * 32;
        float4 e = make_float4(0.f, 0.f, 0.f, 0.f);
        if (gm < M) {
            const float4 a = *(const float4*)(A  + (size_t)gm * F_IN + a_col);
            const float4 m = *(const float4*)(Mk + (size_t)gm * F_IN + a_col);
            e = make_float4(a.x * m.x, a.y * m.y, a.z * m.z, a.w * m.w);
        }
        eA[p] = e;
        wV[p] = *(const float4*)(W + (size_t)(w_row + p * 8) * F_OUT + w_col);
    }

    for (int k0 = 0; k0 < F_IN; k0 += BK) {
        // ---- store staged regs -> smem with hi/lo split ----
#pragma unroll
        for (int p = 0; p < 4; p++) {
            int row = a_row + p * 32;
            split_store(eA[p], &As_hi[row][a_col], &As_lo[row][a_col]);
            int wr = w_row + p * 8;
            split_store(wV[p], &Ws_hi[wr][w_col], &Ws_lo[wr][w_col]);
        }
        __syncthreads();

        // ---- prefetch next chunk's globals (in flight during MMA) ----
        const int kn = k0 + BK;
        if (kn < F_IN) {
#pragma unroll
            for (int p = 0; p < 4; p++) {
                int gm = block_m + a_row + p * 32;
                float4 e = make_float4(0.f, 0.f, 0.f, 0.f);
                if (gm < M) {
                    const float4 a = *(const float4*)(A  + (size_t)gm * F_IN + kn + a_col);
                    const float4 m = *(const float4*)(Mk + (size_t)gm * F_IN + kn + a_col);
                    e = make_float4(a.x * m.x, a.y * m.y, a.z * m.z, a.w * m.w);
                }
                eA[p] = e;
                wV[p] = *(const float4*)(W + (size_t)(kn + w_row + p * 8) * F_OUT + w_col);
            }
        }

        // ---- compute: two k16 steps per chunk ----
#pragma unroll
        for (int k16 = 0; k16 < BK; k16 += 16) {
            uint32_t ah[2][4], al[2][4];
#pragma unroll
            for (int mt = 0; mt < 2; mt++) {
                int r = wm + mt * 16 + aRow;
                int c = k16 + aOff;
                ldm_x4(ah[mt], as_hi_b + (uint32_t)(r * LDA + c) * 2);
                ldm_x4(al[mt], as_lo_b + (uint32_t)(r * LDA + c) * 2);
            }
            uint32_t bh[4][4], bl[4][4];
#pragma unroll
            for (int nq = 0; nq < 4; nq++) {
                int kr = k16 + (lane & 15);
                int c  = wn + nq * 16 + aOff;
                ldm_x4_trans(bh[nq], ws_hi_b + (uint32_t)(kr * LDB + c) * 2);
                ldm_x4_trans(bl[nq], ws_lo_b + (uint32_t)(kr * LDB + c) * 2);
            }
#pragma unroll
            for (int mt = 0; mt < 2; mt++) {
#pragma unroll
                for (int nt = 0; nt < 8; nt++) {
                    const int nq = nt >> 1, pr = (nt & 1) * 2;
                    mma_bf16(acc[mt][nt], ah[mt], bh[nq][pr], bh[nq][pr + 1]);
                    mma_bf16(acc[mt][nt], ah[mt], bl[nq][pr], bl[nq][pr + 1]);
                    mma_bf16(acc[mt][nt], al[mt], bh[nq][pr], bh[nq][pr + 1]);
                }
            }
        }
        __syncthreads();
    }

    // ---- store x tile ----
    const int gid = lane >> 2;
    const int tq  = lane & 3;
#pragma unroll
    for (int mt = 0; mt < 2; mt++) {
        int gm0 = block_m + wm + mt * 16 + gid;
        int gm1 = gm0 + 8;
#pragma unroll
        for (int nt = 0; nt < 8; nt++) {
            int col = wn + nt * 8 + tq * 2;
            if (gm0 < M)
                *(float2*)(g_x + (size_t)gm0 * F_OUT + col) =
                    make_float2(acc[mt][nt][0], acc[mt][nt][1]);
            if (gm1 < M)
                *(float2*)(g_x + (size_t)gm1 * F_OUT + col) =
                    make_float2(acc[mt][nt][2], acc[mt][nt][3]);
        }
    }
}

// ---------------------------------------------------------------------------
// CSR build
// ---------------------------------------------------------------------------
__global__ void zero_deg_kernel(int N)
{
    int i = blockIdx.x * blockDim.x + threadIdx.x;
    if (i < N) g_deg[i] = 0;
}

// hist: 4 edges per thread (int4) for MLP
__global__ void hist_kernel(const int* __restrict__ rows, int E)
{
    int i4 = (blockIdx.x * blockDim.x + threadIdx.x) * 4;
    if (i4 + 3 < E) {
        const int4 r = *(const int4*)(rows + i4);
        atomicAdd(&g_deg[r.x], 1);
        atomicAdd(&g_deg[r.y], 1);
        atomicAdd(&g_deg[r.z], 1);
        atomicAdd(&g_deg[r.w], 1);
    } else {
        for (int i = i4; i < E; i++) atomicAdd(&g_deg[rows[i]], 1);
    }
}

__global__ __launch_bounds__(256)
void scan_blocks_kernel(int N)
{
    __shared__ int sh[256];
    const int tid = threadIdx.x;
    const int i = blockIdx.x * 256 + tid;

    int v = (i < N) ? g_deg[i] : 0;
    int incl = v;
    sh[tid] = incl;
    __syncthreads();
#pragma unroll
    for (int off = 1; off < 256; off <<= 1) {
        int t = (tid >= off) ? sh[tid - off] : 0;
        __syncthreads();
        incl += t;
        sh[tid] = incl;
        __syncthreads();
    }
    if (i < N) g_row_start[i] = incl - v;
    if (tid == 255) g_blk_sum[blockIdx.x] = incl;
}

__global__ __launch_bounds__(512)
void scan_top_kernel(int nblocks)
{
    __shared__ int sh[512];
    const int tid = threadIdx.x;
    int v = (tid < nblocks) ? g_blk_sum[tid] : 0;
    int incl = v;
    sh[tid] = incl;
    __syncthreads();
#pragma unroll
    for (int off = 1; off < 512; off <<= 1) {
        int t = (tid >= off) ? sh[tid - off] : 0;
        __syncthreads();
        incl += t;
        sh[tid] = incl;
        __syncthreads();
    }
    if (tid < nblocks) g_blk_sum[tid] = incl - v;
}

__global__ __launch_bounds__(256)
void scan_add_kernel(int N, int E)
{
    const int i = blockIdx.x * 256 + threadIdx.x;
    if (i < N) {
        int rs = g_row_start[i] + g_blk_sum[blockIdx.x];
        g_row_start[i] = rs;
        g_cursor[i]    = rs;
    }
    if (i == 0) g_row_start[N] = E;
}

// fill: 2 edges per thread for MLP
__global__ void fill_kernel(const int*   __restrict__ rows,
                            const int*   __restrict__ cols,
                            const float* __restrict__ vals,
                            int E)
{
    int i2 = (blockIdx.x * blockDim.x + threadIdx.x) * 2;
    if (i2 + 1 < E) {
        const int2   r = *(const int2*)(rows + i2);
        const int2   c = *(const int2*)(cols + i2);
        const float2 v = *(const float2*)(vals + i2);
        int p0 = atomicAdd(&g_cursor[r.x], 1);
        int p1 = atomicAdd(&g_cursor[r.y], 1);
        g_edges[p0] = make_uint2((unsigned)c.x, __float_as_uint(v.x));
        g_edges[p1] = make_uint2((unsigned)c.y, __float_as_uint(v.y));
    } else if (i2 < E) {
        int pos = atomicAdd(&g_cursor[rows[i2]], 1);
        g_edges[pos] = make_uint2((unsigned)cols[i2], __float_as_uint(vals[i2]));
    }
}

// ---------------------------------------------------------------------------
// Kernel 5: row-parallel SpMM + bias + ReLU (one warp per output row)
// ---------------------------------------------------------------------------
__global__ __launch_bounds__(256)
void spmm_csr_kernel(const float* __restrict__ b,
                     float*       __restrict__ out,
                     int N)
{
    const int warp_in_blk = threadIdx.x >> 5;
    const int lane = threadIdx.x & 31;
    const int row  = blockIdx.x * 8 + warp_in_blk;
    if (row >= N) return;

    const int s = g_row_start[row];
    const int e = g_row_start[row + 1];

    float4 acc = make_float4(0.f, 0.f, 0.f, 0.f);

    int j = s;
    for (; j + 4 <= e; j += 4) {
        const uint2 e0 = g_edges[j];
        const uint2 e1 = g_edges[j + 1];
        const uint2 e2 = g_edges[j + 2];
        const uint2 e3 = g_edges[j + 3];
        const float4 a0 = __ldg((const float4*)(g_x + (size_t)e0.x * F_OUT) + lane);
        const float4 a1 = __ldg((const float4*)(g_x + (size_t)e1.x * F_OUT) + lane);
        const float4 a2 = __ldg((const float4*)(g_x + (size_t)e2.x * F_OUT) + lane);
        const float4 a3 = __ldg((const float4*)(g_x + (size_t)e3.x * F_OUT) + lane);
        const float v0 = __uint_as_float(e0.y);
        const float v1 = __uint_as_float(e1.y);
        const float v2 = __uint_as_float(e2.y);
        const float v3 = __uint_as_float(e3.y);
        acc.x = fmaf(v0, a0.x, acc.x); acc.y = fmaf(v0, a0.y, acc.y);
        acc.z = fmaf(v0, a0.z, acc.z); acc.w = fmaf(v0, a0.w, acc.w);
        acc.x = fmaf(v1, a1.x, acc.x); acc.y = fmaf(v1, a1.y, acc.y);
        acc.z = fmaf(v1, a1.z, acc.z); acc.w = fmaf(v1, a1.w, acc.w);
        acc.x = fmaf(v2, a2.x, acc.x); acc.y = fmaf(v2, a2.y, acc.y);
        acc.z = fmaf(v2, a2.z, acc.z); acc.w = fmaf(v2, a2.w, acc.w);
        acc.x = fmaf(v3, a3.x, acc.x); acc.y = fmaf(v3, a3.y, acc.y);
        acc.z = fmaf(v3, a3.z, acc.z); acc.w = fmaf(v3, a3.w, acc.w);
    }
    for (; j < e; j++) {
        const uint2 e0 = g_edges[j];
        const float4 a0 = __ldg((const float4*)(g_x + (size_t)e0.x * F_OUT) + lane);
        const float v0 = __uint_as_float(e0.y);
        acc.x = fmaf(v0, a0.x, acc.x); acc.y = fmaf(v0, a0.y, acc.y);
        acc.z = fmaf(v0, a0.z, acc.z); acc.w = fmaf(v0, a0.w, acc.w);
    }

    const float4 bb = ((const float4*)b)[lane];
    float4 r;
    r.x = fmaxf(acc.x + bb.x, 0.f);
    r.y = fmaxf(acc.y + bb.y, 0.f);
    r.z = fmaxf(acc.z + bb.z, 0.f);
    r.w = fmaxf(acc.w + bb.w, 0.f);
    ((float4*)(out + (size_t)row * F_OUT))[lane] = r;
}

// ---------------------------------------------------------------------------
extern "C" void kernel_launch(void* const* d_in, const int* in_sizes, int n_in,
                              void* d_out, int out_size)
{
    const float* features  = (const float*)d_in[0];  // [N, 512]
    const float* drop_mask = (const float*)d_in[1];  // [N, 512]
    const float* W         = (const float*)d_in[2];  // [512, 128]
    const float* b         = (const float*)d_in[3];  // [128]
    const int*   adj_rows  = (const int*)d_in[4];    // [E]
    const int*   adj_cols  = (const int*)d_in[5];    // [E]
    const float* adj_vals  = (const float*)d_in[6];  // [E]
    float* out = (float*)d_out;                      // [N, 128]

    const int M = in_sizes[0] / F_IN;
    const int E = in_sizes[4];
    const int nscan = (M + 255) / 256;

    // Fork a side stream for the CSR build so it overlaps the GEMM.
    cudaStream_t s2;
    cudaStreamCreateWithFlags(&s2, cudaStreamNonBlocking);
    cudaEvent_t evFork, evJoin;
    cudaEventCreateWithFlags(&evFork, cudaEventDisableTiming);
    cudaEventCreateWithFlags(&evJoin, cudaEventDisableTiming);

    cudaEventRecord(evFork, 0);
    cudaStreamWaitEvent(s2, evFork, 0);

    // branch A (main stream): GEMM
    gemm_dropout_mma_kernel<<<(M + BM - 1) / BM, 256>>>(features, drop_mask, W, M);

    // branch B (s2): CSR build
    zero_deg_kernel<<<(M + 255) / 256, 256, 0, s2>>>(M);
    hist_kernel<<<(E / 4 + 255) / 256, 256, 0, s2>>>(adj_rows, E);
    scan_blocks_kernel<<<nscan, 256, 0, s2>>>(M);
    scan_top_kernel<<<1, 512, 0, s2>>>(nscan);
    scan_add_kernel<<<nscan, 256, 0, s2>>>(M, E);
    fill_kernel<<<(E / 2 + 255) / 256, 256, 0, s2>>>(adj_rows, adj_cols, adj_vals, E);

    // join: main stream waits for CSR build
    cudaEventRecord(evJoin, s2);
    cudaStreamWaitEvent(0, evJoin, 0);

    // SpMM + bias + ReLU (needs both branches)
    spmm_csr_kernel<<<(M + 7) / 8, 256>>>(b, out, M);
}

// round 12
// speedup vs baseline: 1.7691x; 1.0972x over previous
#include <cuda_runtime.h>
#include <cuda_fp16.h>
#include <cstdint>

// Problem constants (fixed by the dataset)
#define F_IN   512
#define F_OUT  128
#define MAX_N  50048
#define MAX_E  1700000

// Scratch for x = (features * drop_mask) @ W   [N, F_OUT]
__device__ float g_x[(size_t)MAX_N * F_OUT];

// CSR scratch
__device__ int   g_deg[MAX_N];
__device__ int   g_row_start[MAX_N + 1];
__device__ int   g_cursor[MAX_N];
__device__ int   g_blk_sum[512];
__device__ uint2 g_edges[MAX_E];   // .x = col, .y = bits(val)

// ---------------------------------------------------------------------------
// MMA helpers (fp16 path)
// ---------------------------------------------------------------------------
#define BM 128
#define BK 32
#define LDA 40    // As row length (half) with +8 pad: conflict-free ldmatrix
#define LDB 136   // Ws row length (half) with +8 pad

__device__ __forceinline__ void ldm_x4(uint32_t* f, uint32_t addr)
{
    asm volatile("ldmatrix.sync.aligned.m8n8.x4.shared.b16 {%0,%1,%2,%3}, [%4];"
                 : "=r"(f[0]), "=r"(f[1]), "=r"(f[2]), "=r"(f[3]) : "r"(addr));
}

__device__ __forceinline__ void ldm_x4_trans(uint32_t* f, uint32_t addr)
{
    asm volatile("ldmatrix.sync.aligned.m8n8.x4.trans.shared.b16 {%0,%1,%2,%3}, [%4];"
                 : "=r"(f[0]), "=r"(f[1]), "=r"(f[2]), "=r"(f[3]) : "r"(addr));
}

__device__ __forceinline__ void mma_f16(float* c, const uint32_t* a,
                                        uint32_t b0, uint32_t b1)
{
    asm volatile(
        "mma.sync.aligned.m16n8k16.row.col.f32.f16.f16.f32 "
        "{%0,%1,%2,%3}, {%4,%5,%6,%7}, {%8,%9}, {%0,%1,%2,%3};"
        : "+f"(c[0]), "+f"(c[1]), "+f"(c[2]), "+f"(c[3])
        : "r"(a[0]), "r"(a[1]), "r"(a[2]), "r"(a[3]), "r"(b0), "r"(b1));
}

__device__ __forceinline__ uint32_t smem_u32(const void* p)
{
    uint32_t r;
    asm("{.reg .u64 t; cvta.to.shared.u64 t, %1; cvt.u32.u64 %0, t;}"
        : "=r"(r) : "l"(p));
    return r;
}

__device__ __forceinline__ uint32_t pack_h2(float lo_val, float hi_val)
{
    __half2 h = __floats2half2_rn(lo_val, hi_val); // .x = lo_val
    return *(uint32_t*)&h;
}

// split one float4 of A into fp16 hi + fp16 residual, store both
__device__ __forceinline__ void split_store_A(const float4 e,
                                              __half* hi_dst, __half* lo_dst)
{
    float eh[4], el[4];
    const float ev[4] = {e.x, e.y, e.z, e.w};
#pragma unroll
    for (int q = 0; q < 4; q++) {
        __half h = __float2half_rn(ev[q]);
        eh[q] = __half2float(h);
        el[q] = ev[q] - eh[q];
    }
    uint2 hw, lw;
    hw.x = pack_h2(eh[0], eh[1]); hw.y = pack_h2(eh[2], eh[3]);
    lw.x = pack_h2(el[0], el[1]); lw.y = pack_h2(el[2], el[3]);
    *(uint2*)hi_dst = hw;
    *(uint2*)lo_dst = lw;
}

// ---------------------------------------------------------------------------
// Kernel 1: fused dropout + fp16 2-term tensor-core GEMM
// x ~= Ah*Wh + Al*Wh  (Wh = fp16(W), A split; fp32 accum; err ~1.4e-4)
// Register-staged double buffering (from R10).
// ---------------------------------------------------------------------------
__global__ __launch_bounds__(256)
void gemm_dropout_mma_kernel(const float* __restrict__ A,
                             const float* __restrict__ Mk,
                             const float* __restrict__ W,
                             int M)
{
    __shared__ __half As_hi[BM][LDA];
    __shared__ __half As_lo[BM][LDA];
    __shared__ __half Ws[BK][LDB];

    const int tid  = threadIdx.x;
    const int warp = tid >> 5;
    const int lane = tid & 31;
    const int block_m = blockIdx.x * BM;

    const int wm = (warp & 3) * 32;   // warp m-offset (0,32,64,96)
    const int wn = (warp >> 2) * 64;  // warp n-offset (0,64)

    const int aRow = lane & 15;
    const int aOff = (lane >> 4) * 8;

    // per-thread fill geometry (constant across chunks)
    const int a_row  = tid >> 3;           // + p*32: rows 0..127
    const int a_col  = (tid & 7) * 4;      // 0..28
    const int w_row  = tid >> 5;           // + p*8: rows 0..31
    const int w_col  = (tid & 31) * 4;     // 0..124

    float acc[2][8][4];
#pragma unroll
    for (int mt = 0; mt < 2; mt++)
#pragma unroll
        for (int nt = 0; nt < 8; nt++)
#pragma unroll
            for (int q = 0; q < 4; q++) acc[mt][nt][q] = 0.f;

    const uint32_t as_hi_b = smem_u32(&As_hi[0][0]);
    const uint32_t as_lo_b = smem_u32(&As_lo[0][0]);
    const uint32_t ws_b    = smem_u32(&Ws[0][0]);

    // ---- prologue: load chunk 0 into registers ----
    float4 eA[4];
    float4 wV[4];
#pragma unroll
    for (int p = 0; p < 4; p++) {
        int gm = block_m + a_row + p * 32;
        float4 e = make_float4(0.f, 0.f, 0.f, 0.f);
        if (gm < M) {
            const float4 a = *(const float4*)(A  + (size_t)gm * F_IN + a_col);
            const float4 m = *(const float4*)(Mk + (size_t)gm * F_IN + a_col);
            e = make_float4(a.x * m.x, a.y * m.y, a.z * m.z, a.w * m.w);
        }
        eA[p] = e;
        wV[p] = *(const float4*)(W + (size_t)(w_row + p * 8) * F_OUT + w_col);
    }

    for (int k0 = 0; k0 < F_IN; k0 += BK) {
        // ---- store staged regs -> smem ----
#pragma unroll
        for (int p = 0; p < 4; p++) {
            int row = a_row + p * 32;
            split_store_A(eA[p], &As_hi[row][a_col], &As_lo[row][a_col]);
            int wr = w_row + p * 8;
            uint2 wp;
            wp.x = pack_h2(wV[p].x, wV[p].y);
            wp.y = pack_h2(wV[p].z, wV[p].w);
            *(uint2*)&Ws[wr][w_col] = wp;
        }
        __syncthreads();

        // ---- prefetch next chunk's globals ----
        const int kn = k0 + BK;
        if (kn < F_IN) {
#pragma unroll
            for (int p = 0; p < 4; p++) {
                int gm = block_m + a_row + p * 32;
                float4 e = make_float4(0.f, 0.f, 0.f, 0.f);
                if (gm < M) {
                    const float4 a = *(const float4*)(A  + (size_t)gm * F_IN + kn + a_col);
                    const float4 m = *(const float4*)(Mk + (size_t)gm * F_IN + kn + a_col);
                    e = make_float4(a.x * m.x, a.y * m.y, a.z * m.z, a.w * m.w);
                }
                eA[p] = e;
                wV[p] = *(const float4*)(W + (size_t)(kn + w_row + p * 8) * F_OUT + w_col);
            }
        }

        // ---- compute: two k16 steps per chunk ----
#pragma unroll
        for (int k16 = 0; k16 < BK; k16 += 16) {
            uint32_t ah[2][4], al[2][4];
#pragma unroll
            for (int mt = 0; mt < 2; mt++) {
                int r = wm + mt * 16 + aRow;
                int c = k16 + aOff;
                ldm_x4(ah[mt], as_hi_b + (uint32_t)(r * LDA + c) * 2);
                ldm_x4(al[mt], as_lo_b + (uint32_t)(r * LDA + c) * 2);
            }
            uint32_t bw[4][4];
#pragma unroll
            for (int nq = 0; nq < 4; nq++) {
                int kr = k16 + (lane & 15);
                int c  = wn + nq * 16 + aOff;
                ldm_x4_trans(bw[nq], ws_b + (uint32_t)(kr * LDB + c) * 2);
            }
#pragma unroll
            for (int mt = 0; mt < 2; mt++) {
#pragma unroll
                for (int nt = 0; nt < 8; nt++) {
                    const int nq = nt >> 1, pr = (nt & 1) * 2;
                    mma_f16(acc[mt][nt], ah[mt], bw[nq][pr], bw[nq][pr + 1]);
                    mma_f16(acc[mt][nt], al[mt], bw[nq][pr], bw[nq][pr + 1]);
                }
            }
        }
        __syncthreads();
    }

    // ---- store x tile ----
    const int gid = lane >> 2;
    const int tq  = lane & 3;
#pragma unroll
    for (int mt = 0; mt < 2; mt++) {
        int gm0 = block_m + wm + mt * 16 + gid;
        int gm1 = gm0 + 8;
#pragma unroll
        for (int nt = 0; nt < 8; nt++) {
            int col = wn + nt * 8 + tq * 2;
            if (gm0 < M)
                *(float2*)(g_x + (size_t)gm0 * F_OUT + col) =
                    make_float2(acc[mt][nt][0], acc[mt][nt][1]);
            if (gm1 < M)
                *(float2*)(g_x + (size_t)gm1 * F_OUT + col) =
                    make_float2(acc[mt][nt][2], acc[mt][nt][3]);
        }
    }
}

// ---------------------------------------------------------------------------
// CSR build
// ---------------------------------------------------------------------------
__global__ void zero_deg_kernel(int N)
{
    int i = blockIdx.x * blockDim.x + threadIdx.x;
    if (i < N) g_deg[i] = 0;
}

__global__ void hist_kernel(const int* __restrict__ rows, int E)
{
    int i4 = (blockIdx.x * blockDim.x + threadIdx.x) * 4;
    if (i4 + 3 < E) {
        const int4 r = *(const int4*)(rows + i4);
        atomicAdd(&g_deg[r.x], 1);
        atomicAdd(&g_deg[r.y], 1);
        atomicAdd(&g_deg[r.z], 1);
        atomicAdd(&g_deg[r.w], 1);
    } else {
        for (int i = i4; i < E; i++) atomicAdd(&g_deg[rows[i]], 1);
    }
}

__global__ __launch_bounds__(256)
void scan_blocks_kernel(int N)
{
    __shared__ int sh[256];
    const int tid = threadIdx.x;
    const int i = blockIdx.x * 256 + tid;

    int v = (i < N) ? g_deg[i] : 0;
    int incl = v;
    sh[tid] = incl;
    __syncthreads();
#pragma unroll
    for (int off = 1; off < 256; off <<= 1) {
        int t = (tid >= off) ? sh[tid - off] : 0;
        __syncthreads();
        incl += t;
        sh[tid] = incl;
        __syncthreads();
    }
    if (i < N) g_row_start[i] = incl - v;
    if (tid == 255) g_blk_sum[blockIdx.x] = incl;
}

__global__ __launch_bounds__(512)
void scan_top_kernel(int nblocks)
{
    __shared__ int sh[512];
    const int tid = threadIdx.x;
    int v = (tid < nblocks) ? g_blk_sum[tid] : 0;
    int incl = v;
    sh[tid] = incl;
    __syncthreads();
#pragma unroll
    for (int off = 1; off < 512; off <<= 1) {
        int t = (tid >= off) ? sh[tid - off] : 0;
        __syncthreads();
        incl += t;
        sh[tid] = incl;
        __syncthreads();
    }
    if (tid < nblocks) g_blk_sum[tid] = incl - v;
}

__global__ __launch_bounds__(256)
void scan_add_kernel(int N, int E)
{
    const int i = blockIdx.x * 256 + threadIdx.x;
    if (i < N) {
        int rs = g_row_start[i] + g_blk_sum[blockIdx.x];
        g_row_start[i] = rs;
        g_cursor[i]    = rs;
    }
    if (i == 0) g_row_start[N] = E;
}

__global__ void fill_kernel(const int*   __restrict__ rows,
                            const int*   __restrict__ cols,
                            const float* __restrict__ vals,
                            int E)
{
    int i2 = (blockIdx.x * blockDim.x + threadIdx.x) * 2;
    if (i2 + 1 < E) {
        const int2   r = *(const int2*)(rows + i2);
        const int2   c = *(const int2*)(cols + i2);
        const float2 v = *(const float2*)(vals + i2);
        int p0 = atomicAdd(&g_cursor[r.x], 1);
        int p1 = atomicAdd(&g_cursor[r.y], 1);
        g_edges[p0] = make_uint2((unsigned)c.x, __float_as_uint(v.x));
        g_edges[p1] = make_uint2((unsigned)c.y, __float_as_uint(v.y));
    } else if (i2 < E) {
        int pos = atomicAdd(&g_cursor[rows[i2]], 1);
        g_edges[pos] = make_uint2((unsigned)cols[i2], __float_as_uint(vals[i2]));
    }
}

// ---------------------------------------------------------------------------
// Kernel 5: row-parallel SpMM + bias + ReLU (one warp per output row)
// ---------------------------------------------------------------------------
__global__ __launch_bounds__(256)
void spmm_csr_kernel(const float* __restrict__ b,
                     float*       __restrict__ out,
                     int N)
{
    const int warp_in_blk = threadIdx.x >> 5;
    const int lane = threadIdx.x & 31;
    const int row  = blockIdx.x * 8 + warp_in_blk;
    if (row >= N) return;

    const int s = g_row_start[row];
    const int e = g_row_start[row + 1];

    float4 acc = make_float4(0.f, 0.f, 0.f, 0.f);

    int j = s;
    for (; j + 4 <= e; j += 4) {
        const uint2 e0 = g_edges[j];
        const uint2 e1 = g_edges[j + 1];
        const uint2 e2 = g_edges[j + 2];
        const uint2 e3 = g_edges[j + 3];
        const float4 a0 = __ldg((const float4*)(g_x + (size_t)e0.x * F_OUT) + lane);
        const float4 a1 = __ldg((const float4*)(g_x + (size_t)e1.x * F_OUT) + lane);
        const float4 a2 = __ldg((const float4*)(g_x + (size_t)e2.x * F_OUT) + lane);
        const float4 a3 = __ldg((const float4*)(g_x + (size_t)e3.x * F_OUT) + lane);
        const float v0 = __uint_as_float(e0.y);
        const float v1 = __uint_as_float(e1.y);
        const float v2 = __uint_as_float(e2.y);
        const float v3 = __uint_as_float(e3.y);
        acc.x = fmaf(v0, a0.x, acc.x); acc.y = fmaf(v0, a0.y, acc.y);
        acc.z = fmaf(v0, a0.z, acc.z); acc.w = fmaf(v0, a0.w, acc.w);
        acc.x = fmaf(v1, a1.x, acc.x); acc.y = fmaf(v1, a1.y, acc.y);
        acc.z = fmaf(v1, a1.z, acc.z); acc.w = fmaf(v1, a1.w, acc.w);
        acc.x = fmaf(v2, a2.x, acc.x); acc.y = fmaf(v2, a2.y, acc.y);
        acc.z = fmaf(v2, a2.z, acc.z); acc.w = fmaf(v2, a2.w, acc.w);
        acc.x = fmaf(v3, a3.x, acc.x); acc.y = fmaf(v3, a3.y, acc.y);
        acc.z = fmaf(v3, a3.z, acc.z); acc.w = fmaf(v3, a3.w, acc.w);
    }
    for (; j < e; j++) {
        const uint2 e0 = g_edges[j];
        const float4 a0 = __ldg((const float4*)(g_x + (size_t)e0.x * F_OUT) + lane);
        const float v0 = __uint_as_float(e0.y);
        acc.x = fmaf(v0, a0.x, acc.x); acc.y = fmaf(v0, a0.y, acc.y);
        acc.z = fmaf(v0, a0.z, acc.z); acc.w = fmaf(v0, a0.w, acc.w);
    }

    const float4 bb = ((const float4*)b)[lane];
    float4 r;
    r.x = fmaxf(acc.x + bb.x, 0.f);
    r.y = fmaxf(acc.y + bb.y, 0.f);
    r.z = fmaxf(acc.z + bb.z, 0.f);
    r.w = fmaxf(acc.w + bb.w, 0.f);
    ((float4*)(out + (size_t)row * F_OUT))[lane] = r;
}

// ---------------------------------------------------------------------------
extern "C" void kernel_launch(void* const* d_in, const int* in_sizes, int n_in,
                              void* d_out, int out_size)
{
    const float* features  = (const float*)d_in[0];  // [N, 512]
    const float* drop_mask = (const float*)d_in[1];  // [N, 512]
    const float* W         = (const float*)d_in[2];  // [512, 128]
    const float* b         = (const float*)d_in[3];  // [128]
    const int*   adj_rows  = (const int*)d_in[4];    // [E]
    const int*   adj_cols  = (const int*)d_in[5];    // [E]
    const float* adj_vals  = (const float*)d_in[6];  // [E]
    float* out = (float*)d_out;                      // [N, 128]

    const int M = in_sizes[0] / F_IN;
    const int E = in_sizes[4];
    const int nscan = (M + 255) / 256;

    // Fork a side stream for the CSR build so it overlaps the GEMM.
    cudaStream_t s2;
    cudaStreamCreateWithFlags(&s2, cudaStreamNonBlocking);
    cudaEvent_t evFork, evJoin;
    cudaEventCreateWithFlags(&evFork, cudaEventDisableTiming);
    cudaEventCreateWithFlags(&evJoin, cudaEventDisableTiming);

    cudaEventRecord(evFork, 0);
    cudaStreamWaitEvent(s2, evFork, 0);

    // branch A (main stream): GEMM
    gemm_dropout_mma_kernel<<<(M + BM - 1) / BM, 256>>>(features, drop_mask, W, M);

    // branch B (s2): CSR build
    zero_deg_kernel<<<(M + 255) / 256, 256, 0, s2>>>(M);
    hist_kernel<<<(E / 4 + 255) / 256, 256, 0, s2>>>(adj_rows, E);
    scan_blocks_kernel<<<nscan, 256, 0, s2>>>(M);
    scan_top_kernel<<<1, 512, 0, s2>>>(nscan);
    scan_add_kernel<<<nscan, 256, 0, s2>>>(M, E);
    fill_kernel<<<(E / 2 + 255) / 256, 256, 0, s2>>>(adj_rows, adj_cols, adj_vals, E);

    // join: main stream waits for CSR build
    cudaEventRecord(evJoin, s2);
    cudaStreamWaitEvent(0, evJoin, 0);

    // SpMM + bias + ReLU (needs both branches)
    spmm_csr_kernel<<<(M + 7) / 8, 256>>>(b, out, M);
}

// round 13
// speedup vs baseline: 1.9317x; 1.0919x over previous
#include <cuda_runtime.h>
#include <cuda_fp16.h>
#include <cstdint>

// Problem constants (fixed by the dataset)
#define F_IN   512
#define F_OUT  128
#define MAX_N  50048
#define MAX_E  1700000

// Scratch for x = (features * drop_mask) @ W   [N, F_OUT], fp16
__device__ __half g_x[(size_t)MAX_N * F_OUT];

// CSR scratch
__device__ int   g_deg[MAX_N];
__device__ int   g_row_start[MAX_N + 1];
__device__ int   g_cursor[MAX_N];
__device__ int   g_blk_sum[512];
__device__ uint2 g_edges[MAX_E];   // .x = col, .y = bits(val)

// ---------------------------------------------------------------------------
// MMA helpers (fp16 path)
// ---------------------------------------------------------------------------
#define BM 128
#define BK 32
#define LDA 40    // As row length (half) with +8 pad: conflict-free ldmatrix
#define LDB 136   // Ws row length (half) with +8 pad

__device__ __forceinline__ void ldm_x4(uint32_t* f, uint32_t addr)
{
    asm volatile("ldmatrix.sync.aligned.m8n8.x4.shared.b16 {%0,%1,%2,%3}, [%4];"
                 : "=r"(f[0]), "=r"(f[1]), "=r"(f[2]), "=r"(f[3]) : "r"(addr));
}

__device__ __forceinline__ void ldm_x4_trans(uint32_t* f, uint32_t addr)
{
    asm volatile("ldmatrix.sync.aligned.m8n8.x4.trans.shared.b16 {%0,%1,%2,%3}, [%4];"
                 : "=r"(f[0]), "=r"(f[1]), "=r"(f[2]), "=r"(f[3]) : "r"(addr));
}

__device__ __forceinline__ void mma_f16(float* c, const uint32_t* a,
                                        uint32_t b0, uint32_t b1)
{
    asm volatile(
        "mma.sync.aligned.m16n8k16.row.col.f32.f16.f16.f32 "
        "{%0,%1,%2,%3}, {%4,%5,%6,%7}, {%8,%9}, {%0,%1,%2,%3};"
        : "+f"(c[0]), "+f"(c[1]), "+f"(c[2]), "+f"(c[3])
        : "r"(a[0]), "r"(a[1]), "r"(a[2]), "r"(a[3]), "r"(b0), "r"(b1));
}

__device__ __forceinline__ uint32_t smem_u32(const void* p)
{
    uint32_t r;
    asm("{.reg .u64 t; cvta.to.shared.u64 t, %1; cvt.u32.u64 %0, t;}"
        : "=r"(r) : "l"(p));
    return r;
}

__device__ __forceinline__ uint32_t pack_h2(float lo_val, float hi_val)
{
    __half2 h = __floats2half2_rn(lo_val, hi_val); // .x = lo_val
    return *(uint32_t*)&h;
}

// split one float4 of A into fp16 hi + fp16 residual, store both
__device__ __forceinline__ void split_store_A(const float4 e,
                                              __half* hi_dst, __half* lo_dst)
{
    float eh[4], el[4];
    const float ev[4] = {e.x, e.y, e.z, e.w};
#pragma unroll
    for (int q = 0; q < 4; q++) {
        __half h = __float2half_rn(ev[q]);
        eh[q] = __half2float(h);
        el[q] = ev[q] - eh[q];
    }
    uint2 hw, lw;
    hw.x = pack_h2(eh[0], eh[1]); hw.y = pack_h2(eh[2], eh[3]);
    lw.x = pack_h2(el[0], el[1]); lw.y = pack_h2(el[2], el[3]);
    *(uint2*)hi_dst = hw;
    *(uint2*)lo_dst = lw;
}

// unpack 4 halves (uint2) to float4
__device__ __forceinline__ float4 h4_to_f4(uint2 u)
{
    __half2 h0 = *(__half2*)&u.x;
    __half2 h1 = *(__half2*)&u.y;
    float2 f0 = __half22float2(h0);
    float2 f1 = __half22float2(h1);
    return make_float4(f0.x, f0.y, f1.x, f1.y);
}

// ---------------------------------------------------------------------------
// Kernel 1: fused dropout + fp16 2-term tensor-core GEMM
// x ~= Ah*Wh + Al*Wh  (Wh = fp16(W), A split; fp32 accum)
// x stored to global as fp16 (halves SpMM gather traffic).
// ---------------------------------------------------------------------------
__global__ __launch_bounds__(256)
void gemm_dropout_mma_kernel(const float* __restrict__ A,
                             const float* __restrict__ Mk,
                             const float* __restrict__ W,
                             int M)
{
    __shared__ __half As_hi[BM][LDA];
    __shared__ __half As_lo[BM][LDA];
    __shared__ __half Ws[BK][LDB];

    const int tid  = threadIdx.x;
    const int warp = tid >> 5;
    const int lane = tid & 31;
    const int block_m = blockIdx.x * BM;

    const int wm = (warp & 3) * 32;   // warp m-offset (0,32,64,96)
    const int wn = (warp >> 2) * 64;  // warp n-offset (0,64)

    const int aRow = lane & 15;
    const int aOff = (lane >> 4) * 8;

    const int a_row  = tid >> 3;           // + p*32: rows 0..127
    const int a_col  = (tid & 7) * 4;      // 0..28
    const int w_row  = tid >> 5;           // + p*8: rows 0..31
    const int w_col  = (tid & 31) * 4;     // 0..124

    float acc[2][8][4];
#pragma unroll
    for (int mt = 0; mt < 2; mt++)
#pragma unroll
        for (int nt = 0; nt < 8; nt++)
#pragma unroll
            for (int q = 0; q < 4; q++) acc[mt][nt][q] = 0.f;

    const uint32_t as_hi_b = smem_u32(&As_hi[0][0]);
    const uint32_t as_lo_b = smem_u32(&As_lo[0][0]);
    const uint32_t ws_b    = smem_u32(&Ws[0][0]);

    // ---- prologue: load chunk 0 into registers ----
    float4 eA[4];
    float4 wV[4];
#pragma unroll
    for (int p = 0; p < 4; p++) {
        int gm = block_m + a_row + p * 32;
        float4 e = make_float4(0.f, 0.f, 0.f, 0.f);
        if (gm < M) {
            const float4 a = *(const float4*)(A  + (size_t)gm * F_IN + a_col);
            const float4 m = *(const float4*)(Mk + (size_t)gm * F_IN + a_col);
            e = make_float4(a.x * m.x, a.y * m.y, a.z * m.z, a.w * m.w);
        }
        eA[p] = e;
        wV[p] = *(const float4*)(W + (size_t)(w_row + p * 8) * F_OUT + w_col);
    }

    for (int k0 = 0; k0 < F_IN; k0 += BK) {
        // ---- store staged regs -> smem ----
#pragma unroll
        for (int p = 0; p < 4; p++) {
            int row = a_row + p * 32;
            split_store_A(eA[p], &As_hi[row][a_col], &As_lo[row][a_col]);
            int wr = w_row + p * 8;
            uint2 wp;
            wp.x = pack_h2(wV[p].x, wV[p].y);
            wp.y = pack_h2(wV[p].z, wV[p].w);
            *(uint2*)&Ws[wr][w_col] = wp;
        }
        __syncthreads();

        // ---- prefetch next chunk's globals ----
        const int kn = k0 + BK;
        if (kn < F_IN) {
#pragma unroll
            for (int p = 0; p < 4; p++) {
                int gm = block_m + a_row + p * 32;
                float4 e = make_float4(0.f, 0.f, 0.f, 0.f);
                if (gm < M) {
                    const float4 a = *(const float4*)(A  + (size_t)gm * F_IN + kn + a_col);
                    const float4 m = *(const float4*)(Mk + (size_t)gm * F_IN + kn + a_col);
                    e = make_float4(a.x * m.x, a.y * m.y, a.z * m.z, a.w * m.w);
                }
                eA[p] = e;
                wV[p] = *(const float4*)(W + (size_t)(kn + w_row + p * 8) * F_OUT + w_col);
            }
        }

        // ---- compute: two k16 steps per chunk ----
#pragma unroll
        for (int k16 = 0; k16 < BK; k16 += 16) {
            uint32_t ah[2][4], al[2][4];
#pragma unroll
            for (int mt = 0; mt < 2; mt++) {
                int r = wm + mt * 16 + aRow;
                int c = k16 + aOff;
                ldm_x4(ah[mt], as_hi_b + (uint32_t)(r * LDA + c) * 2);
                ldm_x4(al[mt], as_lo_b + (uint32_t)(r * LDA + c) * 2);
            }
            uint32_t bw[4][4];
#pragma unroll
            for (int nq = 0; nq < 4; nq++) {
                int kr = k16 + (lane & 15);
                int c  = wn + nq * 16 + aOff;
                ldm_x4_trans(bw[nq], ws_b + (uint32_t)(kr * LDB + c) * 2);
            }
#pragma unroll
            for (int mt = 0; mt < 2; mt++) {
#pragma unroll
                for (int nt = 0; nt < 8; nt++) {
                    const int nq = nt >> 1, pr = (nt & 1) * 2;
                    mma_f16(acc[mt][nt], ah[mt], bw[nq][pr], bw[nq][pr + 1]);
                    mma_f16(acc[mt][nt], al[mt], bw[nq][pr], bw[nq][pr + 1]);
                }
            }
        }
        __syncthreads();
    }

    // ---- store x tile as fp16 (half2 per acc pair) ----
    const int gid = lane >> 2;
    const int tq  = lane & 3;
#pragma unroll
    for (int mt = 0; mt < 2; mt++) {
        int gm0 = block_m + wm + mt * 16 + gid;
        int gm1 = gm0 + 8;
#pragma unroll
        for (int nt = 0; nt < 8; nt++) {
            int col = wn + nt * 8 + tq * 2;
            if (gm0 < M)
                *(uint32_t*)(g_x + (size_t)gm0 * F_OUT + col) =
                    pack_h2(acc[mt][nt][0], acc[mt][nt][1]);
            if (gm1 < M)
                *(uint32_t*)(g_x + (size_t)gm1 * F_OUT + col) =
                    pack_h2(acc[mt][nt][2], acc[mt][nt][3]);
        }
    }
}

// ---------------------------------------------------------------------------
// CSR build
// ---------------------------------------------------------------------------
__global__ void zero_deg_kernel(int N)
{
    int i = blockIdx.x * blockDim.x + threadIdx.x;
    if (i < N) g_deg[i] = 0;
}

__global__ void hist_kernel(const int* __restrict__ rows, int E)
{
    int i4 = (blockIdx.x * blockDim.x + threadIdx.x) * 4;
    if (i4 + 3 < E) {
        const int4 r = *(const int4*)(rows + i4);
        atomicAdd(&g_deg[r.x], 1);
        atomicAdd(&g_deg[r.y], 1);
        atomicAdd(&g_deg[r.z], 1);
        atomicAdd(&g_deg[r.w], 1);
    } else {
        for (int i = i4; i < E; i++) atomicAdd(&g_deg[rows[i]], 1);
    }
}

__global__ __launch_bounds__(256)
void scan_blocks_kernel(int N)
{
    __shared__ int sh[256];
    const int tid = threadIdx.x;
    const int i = blockIdx.x * 256 + tid;

    int v = (i < N) ? g_deg[i] : 0;
    int incl = v;
    sh[tid] = incl;
    __syncthreads();
#pragma unroll
    for (int off = 1; off < 256; off <<= 1) {
        int t = (tid >= off) ? sh[tid - off] : 0;
        __syncthreads();
        incl += t;
        sh[tid] = incl;
        __syncthreads();
    }
    if (i < N) g_row_start[i] = incl - v;
    if (tid == 255) g_blk_sum[blockIdx.x] = incl;
}

__global__ __launch_bounds__(512)
void scan_top_kernel(int nblocks)
{
    __shared__ int sh[512];
    const int tid = threadIdx.x;
    int v = (tid < nblocks) ? g_blk_sum[tid] : 0;
    int incl = v;
    sh[tid] = incl;
    __syncthreads();
#pragma unroll
    for (int off = 1; off < 512; off <<= 1) {
        int t = (tid >= off) ? sh[tid - off] : 0;
        __syncthreads();
        incl += t;
        sh[tid] = incl;
        __syncthreads();
    }
    if (tid < nblocks) g_blk_sum[tid] = incl - v;
}

__global__ __launch_bounds__(256)
void scan_add_kernel(int N, int E)
{
    const int i = blockIdx.x * 256 + threadIdx.x;
    if (i < N) {
        int rs = g_row_start[i] + g_blk_sum[blockIdx.x];
        g_row_start[i] = rs;
        g_cursor[i]    = rs;
    }
    if (i == 0) g_row_start[N] = E;
}

__global__ void fill_kernel(const int*   __restrict__ rows,
                            const int*   __restrict__ cols,
                            const float* __restrict__ vals,
                            int E)
{
    int i2 = (blockIdx.x * blockDim.x + threadIdx.x) * 2;
    if (i2 + 1 < E) {
        const int2   r = *(const int2*)(rows + i2);
        const int2   c = *(const int2*)(cols + i2);
        const float2 v = *(const float2*)(vals + i2);
        int p0 = atomicAdd(&g_cursor[r.x], 1);
        int p1 = atomicAdd(&g_cursor[r.y], 1);
        g_edges[p0] = make_uint2((unsigned)c.x, __float_as_uint(v.x));
        g_edges[p1] = make_uint2((unsigned)c.y, __float_as_uint(v.y));
    } else if (i2 < E) {
        int pos = atomicAdd(&g_cursor[rows[i2]], 1);
        g_edges[pos] = make_uint2((unsigned)cols[i2], __float_as_uint(vals[i2]));
    }
}

// ---------------------------------------------------------------------------
// Kernel 5: row-parallel SpMM + bias + ReLU (one warp per output row)
// Lane owns 4 fp16 columns (uint2 = 8B per edge per lane).
// ---------------------------------------------------------------------------
__global__ __launch_bounds__(256)
void spmm_csr_kernel(const float* __restrict__ b,
                     float*       __restrict__ out,
                     int N)
{
    const int warp_in_blk = threadIdx.x >> 5;
    const int lane = threadIdx.x & 31;
    const int row  = blockIdx.x * 8 + warp_in_blk;
    if (row >= N) return;

    const int s = g_row_start[row];
    const int e = g_row_start[row + 1];

    float4 acc = make_float4(0.f, 0.f, 0.f, 0.f);

    int j = s;
    for (; j + 4 <= e; j += 4) {
        const uint2 e0 = g_edges[j];
        const uint2 e1 = g_edges[j + 1];
        const uint2 e2 = g_edges[j + 2];
        const uint2 e3 = g_edges[j + 3];
        const float4 a0 = h4_to_f4(__ldg((const uint2*)(g_x + (size_t)e0.x * F_OUT) + lane));
        const float4 a1 = h4_to_f4(__ldg((const uint2*)(g_x + (size_t)e1.x * F_OUT) + lane));
        const float4 a2 = h4_to_f4(__ldg((const uint2*)(g_x + (size_t)e2.x * F_OUT) + lane));
        const float4 a3 = h4_to_f4(__ldg((const uint2*)(g_x + (size_t)e3.x * F_OUT) + lane));
        const float v0 = __uint_as_float(e0.y);
        const float v1 = __uint_as_float(e1.y);
        const float v2 = __uint_as_float(e2.y);
        const float v3 = __uint_as_float(e3.y);
        acc.x = fmaf(v0, a0.x, acc.x); acc.y = fmaf(v0, a0.y, acc.y);
        acc.z = fmaf(v0, a0.z, acc.z); acc.w = fmaf(v0, a0.w, acc.w);
        acc.x = fmaf(v1, a1.x, acc.x); acc.y = fmaf(v1, a1.y, acc.y);
        acc.z = fmaf(v1, a1.z, acc.z); acc.w = fmaf(v1, a1.w, acc.w);
        acc.x = fmaf(v2, a2.x, acc.x); acc.y = fmaf(v2, a2.y, acc.y);
        acc.z = fmaf(v2, a2.z, acc.z); acc.w = fmaf(v2, a2.w, acc.w);
        acc.x = fmaf(v3, a3.x, acc.x); acc.y = fmaf(v3, a3.y, acc.y);
        acc.z = fmaf(v3, a3.z, acc.z); acc.w = fmaf(v3, a3.w, acc.w);
    }
    for (; j < e; j++) {
        const uint2 e0 = g_edges[j];
        const float4 a0 = h4_to_f4(__ldg((const uint2*)(g_x + (size_t)e0.x * F_OUT) + lane));
        const float v0 = __uint_as_float(e0.y);
        acc.x = fmaf(v0, a0.x, acc.x); acc.y = fmaf(v0, a0.y, acc.y);
        acc.z = fmaf(v0, a0.z, acc.z); acc.w = fmaf(v0, a0.w, acc.w);
    }

    const float4 bb = ((const float4*)b)[lane];
    float4 r;
    r.x = fmaxf(acc.x + bb.x, 0.f);
    r.y = fmaxf(acc.y + bb.y, 0.f);
    r.z = fmaxf(acc.z + bb.z, 0.f);
    r.w = fmaxf(acc.w + bb.w, 0.f);
    ((float4*)(out + (size_t)row * F_OUT))[lane] = r;
}

// ---------------------------------------------------------------------------
extern "C" void kernel_launch(void* const* d_in, const int* in_sizes, int n_in,
                              void* d_out, int out_size)
{
    const float* features  = (const float*)d_in[0];  // [N, 512]
    const float* drop_mask = (const float*)d_in[1];  // [N, 512]
    const float* W         = (const float*)d_in[2];  // [512, 128]
    const float* b         = (const float*)d_in[3];  // [128]
    const int*   adj_rows  = (const int*)d_in[4];    // [E]
    const int*   adj_cols  = (const int*)d_in[5];    // [E]
    const float* adj_vals  = (const float*)d_in[6];  // [E]
    float* out = (float*)d_out;                      // [N, 128]

    const int M = in_sizes[0] / F_IN;
    const int E = in_sizes[4];
    const int nscan = (M + 255) / 256;

    // Fork a side stream for the CSR build so it overlaps the GEMM.
    cudaStream_t s2;
    cudaStreamCreateWithFlags(&s2, cudaStreamNonBlocking);
    cudaEvent_t evFork, evJoin;
    cudaEventCreateWithFlags(&evFork, cudaEventDisableTiming);
    cudaEventCreateWithFlags(&evJoin, cudaEventDisableTiming);

    cudaEventRecord(evFork, 0);
    cudaStreamWaitEvent(s2, evFork, 0);

    // branch A (main stream): GEMM
    gemm_dropout_mma_kernel<<<(M + BM - 1) / BM, 256>>>(features, drop_mask, W, M);

    // branch B (s2): CSR build
    zero_deg_kernel<<<(M + 255) / 256, 256, 0, s2>>>(M);
    hist_kernel<<<(E / 4 + 255) / 256, 256, 0, s2>>>(adj_rows, E);
    scan_blocks_kernel<<<nscan, 256, 0, s2>>>(M);
    scan_top_kernel<<<1, 512, 0, s2>>>(nscan);
    scan_add_kernel<<<nscan, 256, 0, s2>>>(M, E);
    fill_kernel<<<(E / 2 + 255) / 256, 256, 0, s2>>>(adj_rows, adj_cols, adj_vals, E);

    // join: main stream waits for CSR build
    cudaEventRecord(evJoin, s2);
    cudaStreamWaitEvent(0, evJoin, 0);

    // SpMM + bias + ReLU (needs both branches)
    spmm_csr_kernel<<<(M + 7) / 8, 256>>>(b, out, M);
}